// round 1
// baseline (speedup 1.0000x reference)
#include <cuda_runtime.h>
#include <math_constants.h>
#include <cstddef>

#define B_   16
#define N_   4096
#define S_   1024
#define K_   32
#define CF_  64

// scratch (no device allocation allowed)
__device__ int g_knn[B_ * S_ * K_];

// ============================================================================
// 1) Farthest point sampling — one block per batch, 1024 threads, 4 pts/thread
//    Must match reference bit-exactly (argmax first-index ties, no FMA).
// ============================================================================
__global__ void fps_kernel(const float* __restrict__ xyz, float* newxyz)
{
    extern __shared__ float sm[];
    float* sx = sm;
    float* sy = sm + N_;
    float* sz = sm + 2 * N_;
    __shared__ float rv[32];
    __shared__ int   ri[32];
    __shared__ int   sfar;

    const int b = blockIdx.x;
    const int t = threadIdx.x;
    const float* base = xyz + (size_t)b * N_ * 3;

    float px[4], py[4], pz[4], dd[4];
#pragma unroll
    for (int j = 0; j < 4; j++) {
        int p = t + j * 1024;
        float x = base[3 * p + 0];
        float y = base[3 * p + 1];
        float z = base[3 * p + 2];
        px[j] = x; py[j] = y; pz[j] = z;
        sx[p] = x; sy[p] = y; sz[p] = z;
        dd[j] = 1e10f;
    }
    if (t == 0) sfar = 0;
    __syncthreads();

    const int lane = t & 31;
    const int warp = t >> 5;

    for (int it = 0; it < S_; it++) {
        const int far = sfar;
        const float cx = sx[far], cy = sy[far], cz = sz[far];

        float bv = -1.0f;
        int   bi = 0;
#pragma unroll
        for (int j = 0; j < 4; j++) {
            float dx = __fsub_rn(px[j], cx);
            float dy = __fsub_rn(py[j], cy);
            float dz = __fsub_rn(pz[j], cz);
            // ((dx*dx + dy*dy) + dz*dz), no FMA contraction
            float d2 = __fadd_rn(__fadd_rn(__fmul_rn(dx, dx), __fmul_rn(dy, dy)),
                                 __fmul_rn(dz, dz));
            float nd = fminf(dd[j], d2);
            dd[j] = nd;
            // ascending indices within thread -> strict > keeps first max
            if (nd > bv) { bv = nd; bi = t + j * 1024; }
        }
        // warp argmax (ties: lower index)
#pragma unroll
        for (int off = 16; off; off >>= 1) {
            float ov = __shfl_down_sync(0xffffffffu, bv, off);
            int   oi = __shfl_down_sync(0xffffffffu, bi, off);
            if (ov > bv || (ov == bv && oi < bi)) { bv = ov; bi = oi; }
        }
        if (lane == 0) { rv[warp] = bv; ri[warp] = bi; }
        __syncthreads();
        if (warp == 0) {
            bv = rv[lane];
            bi = ri[lane];
#pragma unroll
            for (int off = 16; off; off >>= 1) {
                float ov = __shfl_down_sync(0xffffffffu, bv, off);
                int   oi = __shfl_down_sync(0xffffffffu, bi, off);
                if (ov > bv || (ov == bv && oi < bi)) { bv = ov; bi = oi; }
            }
            if (lane == 0) {
                sfar = bi;
                float* o = newxyz + (size_t)(b * S_ + it) * 3;
                o[0] = sx[bi]; o[1] = sy[bi]; o[2] = sz[bi];
            }
        }
        __syncthreads();
    }
}

// ============================================================================
// 2) 32-NN per (b,s): d2 row in smem, 32 x argmin (stable ties = lower index)
// ============================================================================
__global__ void knn_kernel(const float* __restrict__ xyz, const float* newxyz)
{
    __shared__ float d2s[N_];
    __shared__ float rv[8];
    __shared__ int   ri[8];

    const int row = blockIdx.x;          // b*1024 + s
    const int b   = row >> 10;
    const int t   = threadIdx.x;

    const float qx = newxyz[row * 3 + 0];
    const float qy = newxyz[row * 3 + 1];
    const float qz = newxyz[row * 3 + 2];
    const float a2 = __fadd_rn(__fadd_rn(__fmul_rn(qx, qx), __fmul_rn(qy, qy)),
                               __fmul_rn(qz, qz));

    const float* base = xyz + (size_t)b * N_ * 3;
    for (int i = t; i < N_; i += 256) {
        float x = base[3 * i + 0];
        float y = base[3 * i + 1];
        float z = base[3 * i + 2];
        float b2 = __fadd_rn(__fadd_rn(__fmul_rn(x, x), __fmul_rn(y, y)),
                             __fmul_rn(z, z));
        float ab = __fadd_rn(__fadd_rn(__fmul_rn(qx, x), __fmul_rn(qy, y)),
                             __fmul_rn(qz, z));
        float d2 = fmaxf(__fadd_rn(__fsub_rn(a2, __fmul_rn(2.0f, ab)), b2), 0.0f);
        d2s[i] = d2;
    }
    __syncthreads();

    const int lane = t & 31;
    const int warp = t >> 5;

    for (int sel = 0; sel < K_; sel++) {
        float bv = CUDART_INF_F;
        int   bi = 1 << 30;
        for (int i = t; i < N_; i += 256) {
            float v = d2s[i];
            if (v < bv) { bv = v; bi = i; }   // ascending i -> strict < keeps first
        }
#pragma unroll
        for (int off = 16; off; off >>= 1) {
            float ov = __shfl_down_sync(0xffffffffu, bv, off);
            int   oi = __shfl_down_sync(0xffffffffu, bi, off);
            if (ov < bv || (ov == bv && oi < bi)) { bv = ov; bi = oi; }
        }
        if (lane == 0) { rv[warp] = bv; ri[warp] = bi; }
        __syncthreads();
        if (t == 0) {
            float v = rv[0]; int i0 = ri[0];
#pragma unroll
            for (int w = 1; w < 8; w++) {
                if (rv[w] < v || (rv[w] == v && ri[w] < i0)) { v = rv[w]; i0 = ri[w]; }
            }
            g_knn[(size_t)row * K_ + sel] = i0;
            d2s[i0] = CUDART_INF_F;
        }
        __syncthreads();
    }
}

// ============================================================================
// 3) Fused gather + 3-layer MLP (1x1 conv + relu + BN) + max-pool over K
//    One block (128 thr) per (b,s). Each thread: 2 k-rows x (Cout/8) cols.
// ============================================================================
template <int CIN, int COUT>
__device__ __forceinline__ void layer_compute(
    const float* inb, int sin, float* outb, int sout,
    const float* __restrict__ Wg, const float* __restrict__ bg,
    const float* __restrict__ gg, const float* __restrict__ beg,
    const float* __restrict__ mg, const float* __restrict__ vg,
    float* Wsm, float* bsm, float* ssm, float* tsm, int t)
{
    __syncthreads();  // previous layer consumers done before Wsm overwrite
    for (int i = t; i < CIN * COUT; i += 128) Wsm[i] = Wg[i];
    if (t < COUT) {
        float sc = gg[t] * rsqrtf(vg[t] + 1e-3f);
        ssm[t] = sc;
        tsm[t] = beg[t] - mg[t] * sc;
        bsm[t] = bg[t];
    }
    __syncthreads();

    constexpr int CO = COUT / 8;          // 8 (Cout=64) or 16 (Cout=128)
    const int kp  = t >> 3;               // 0..15  -> k rows {kp, kp+16}
    const int cg  = t & 7;
    const int co0 = cg * CO;

    const float* in0 = inb + kp * sin;
    const float* in1 = inb + (kp + 16) * sin;

    float acc0[CO], acc1[CO];
#pragma unroll
    for (int u = 0; u < CO; u++) { acc0[u] = 0.0f; acc1[u] = 0.0f; }

    for (int ci = 0; ci < CIN; ci++) {
        float a0 = in0[ci];
        float a1 = in1[ci];
        const float4* wr = (const float4*)(Wsm + ci * COUT + co0);
#pragma unroll
        for (int u = 0; u < CO / 4; u++) {
            float4 w = wr[u];
            acc0[4 * u + 0] += a0 * w.x;  acc1[4 * u + 0] += a1 * w.x;
            acc0[4 * u + 1] += a0 * w.y;  acc1[4 * u + 1] += a1 * w.y;
            acc0[4 * u + 2] += a0 * w.z;  acc1[4 * u + 2] += a1 * w.z;
            acc0[4 * u + 3] += a0 * w.w;  acc1[4 * u + 3] += a1 * w.w;
        }
    }

    float* o0 = outb + kp * sout + co0;
    float* o1 = outb + (kp + 16) * sout + co0;
#pragma unroll
    for (int u = 0; u < CO; u++) {
        int co = co0 + u;
        float r0 = fmaxf(acc0[u] + bsm[co], 0.0f);
        float r1 = fmaxf(acc1[u] + bsm[co], 0.0f);
        o0[u] = r0 * ssm[co] + tsm[co];
        o1[u] = r1 * ssm[co] + tsm[co];
    }
    // next layer's entry __syncthreads() orders these writes vs. reads
}

__global__ void mlp_kernel(
    const float* __restrict__ xyz, const float* __restrict__ feat,
    const float* newxyz,
    const float* __restrict__ W0, const float* __restrict__ b0,
    const float* __restrict__ g0, const float* __restrict__ be0,
    const float* __restrict__ m0, const float* __restrict__ v0,
    const float* __restrict__ W1, const float* __restrict__ b1,
    const float* __restrict__ g1, const float* __restrict__ be1,
    const float* __restrict__ m1, const float* __restrict__ v1,
    const float* __restrict__ W2, const float* __restrict__ b2,
    const float* __restrict__ g2, const float* __restrict__ be2,
    const float* __restrict__ m2, const float* __restrict__ v2,
    float* outp)
{
    extern __shared__ float sm[];
    float* bufA = sm;                    // 32 x 68
    float* bufB = bufA + 32 * 68;        // 32 x 132
    float* Wsm  = bufB + 32 * 132;       // up to 64*128
    float* bsm  = Wsm + 64 * 128;        // 128
    float* ssm  = bsm + 128;
    float* tsm  = ssm + 128;
    __shared__ int   sidx[K_];
    __shared__ float q[3];

    const int t   = threadIdx.x;
    const int row = blockIdx.x;          // b*1024 + s
    const int b   = row >> 10;

    if (t < K_) sidx[t] = g_knn[(size_t)row * K_ + t];
    if (t < 3)  q[t] = newxyz[row * 3 + t];
    __syncthreads();

    // gather [grouped_xyz(3) | features(64)] into bufA: 4 threads per k
    {
        const int k = t >> 2, l = t & 3;
        const int id = sidx[k];
        const float* fr = feat + ((size_t)(b * N_) + id) * CF_;
        float* dst = bufA + k * 68;
        if (l == 0) {
            const float* xr = xyz + ((size_t)(b * N_) + id) * 3;
            dst[0] = __fsub_rn(xr[0], q[0]);
            dst[1] = __fsub_rn(xr[1], q[1]);
            dst[2] = __fsub_rn(xr[2], q[2]);
        }
#pragma unroll
        for (int j = 0; j < 4; j++) {
            float4 v = *(const float4*)(fr + (l + 4 * j) * 4);
            float* d = dst + 3 + (l + 4 * j) * 4;
            d[0] = v.x; d[1] = v.y; d[2] = v.z; d[3] = v.w;
        }
    }

    layer_compute<67, 64 >(bufA, 68,  bufB, 132, W0, b0, g0, be0, m0, v0, Wsm, bsm, ssm, tsm, t);
    layer_compute<64, 64 >(bufB, 132, bufA, 68,  W1, b1, g1, be1, m1, v1, Wsm, bsm, ssm, tsm, t);
    layer_compute<64, 128>(bufA, 68,  bufB, 132, W2, b2, g2, be2, m2, v2, Wsm, bsm, ssm, tsm, t);
    __syncthreads();

    // max-pool over k (128 threads = 128 channels; stride 132 -> conflict-free)
    {
        float m = -CUDART_INF_F;
#pragma unroll
        for (int k = 0; k < K_; k++) m = fmaxf(m, bufB[k * 132 + t]);
        outp[(size_t)row * 128 + t] = m;
    }
}

// ============================================================================
extern "C" void kernel_launch(void* const* d_in, const int* in_sizes, int n_in,
                              void* d_out, int out_size)
{
    (void)in_sizes; (void)n_in; (void)out_size;
    const float* xyz  = (const float*)d_in[0];
    const float* feat = (const float*)d_in[1];
    const float* P[18];
    for (int i = 0; i < 18; i++) P[i] = (const float*)d_in[2 + i];

    float* out     = (float*)d_out;
    float* newxyz  = out;                              // 16*1024*3
    float* pooled  = out + (size_t)B_ * S_ * 3;        // 16*1024*128

    const int fps_smem = 3 * N_ * 4;                                   // 49152
    const int mlp_smem = (32 * 68 + 32 * 132 + 64 * 128 + 3 * 128) * 4; // 59904

    cudaFuncSetAttribute(fps_kernel, cudaFuncAttributeMaxDynamicSharedMemorySize, fps_smem);
    cudaFuncSetAttribute(mlp_kernel, cudaFuncAttributeMaxDynamicSharedMemorySize, mlp_smem);

    fps_kernel<<<B_, 1024, fps_smem>>>(xyz, newxyz);
    knn_kernel<<<B_ * S_, 256>>>(xyz, newxyz);
    mlp_kernel<<<B_ * S_, 128, mlp_smem>>>(
        xyz, feat, newxyz,
        P[0],  P[1],  P[2],  P[3],  P[4],  P[5],
        P[6],  P[7],  P[8],  P[9],  P[10], P[11],
        P[12], P[13], P[14], P[15], P[16], P[17],
        pooled);
}

// round 3
// speedup vs baseline: 1.4911x; 1.4911x over previous
#include <cuda_runtime.h>
#include <math_constants.h>
#include <cstddef>

#define B_   16
#define N_   4096
#define S_   1024
#define K_   32
#define CF_  64

// device scratch (no allocation allowed)
__device__ int   g_knn[B_ * S_ * K_];
__device__ float g_fW0[B_ * N_ * 64];     // feat @ W0[3:67]  (16 MB)

// ---------------------------------------------------------------- f32x2 helpers
__device__ __forceinline__ unsigned long long pack2(float a) {
    unsigned long long r;
    asm("mov.b64 %0, {%1, %1};" : "=l"(r) : "f"(a));
    return r;
}
__device__ __forceinline__ void fma2(unsigned long long& d,
                                     unsigned long long a, unsigned long long b) {
    asm("fma.rn.f32x2 %0, %1, %2, %0;" : "+l"(d) : "l"(a), "l"(b));
}
__device__ __forceinline__ float2 unpack2(unsigned long long v) {
    float2 f;
    asm("mov.b64 {%0, %1}, %2;" : "=f"(f.x), "=f"(f.y) : "l"(v));
    return f;
}

// ============================================================================
// 1) FPS — one block/batch, 1024 thr, REDUX reductions, single barrier/iter
// ============================================================================
__global__ void __launch_bounds__(1024) fps_kernel(const float* __restrict__ xyz,
                                                   float* __restrict__ newxyz)
{
    extern __shared__ float sm[];
    float* sx = sm;
    float* sy = sm + N_;
    float* sz = sm + 2 * N_;
    __shared__ unsigned pv[2][32];
    __shared__ int      pi[2][32];

    const int b = blockIdx.x;
    const int t = threadIdx.x;
    const int lane = t & 31, warp = t >> 5;
    const float* base = xyz + (size_t)b * N_ * 3;

    float px[4], py[4], pz[4], dd[4];
#pragma unroll
    for (int j = 0; j < 4; j++) {
        int p = t + j * 1024;
        float x = base[3 * p + 0], y = base[3 * p + 1], z = base[3 * p + 2];
        px[j] = x; py[j] = y; pz[j] = z;
        sx[p] = x; sy[p] = y; sz[p] = z;
        dd[j] = 1e10f;
    }
    __syncthreads();

    int far = 0;
    for (int it = 0; it < S_; it++) {
        const int pr = it & 1;
        const float cx = sx[far], cy = sy[far], cz = sz[far];

        unsigned bvu = 0u;
        int      bi  = 0x7fffffff;
#pragma unroll
        for (int j = 0; j < 4; j++) {
            float dx = __fsub_rn(px[j], cx);
            float dy = __fsub_rn(py[j], cy);
            float dz = __fsub_rn(pz[j], cz);
            float d2 = __fadd_rn(__fadd_rn(__fmul_rn(dx, dx), __fmul_rn(dy, dy)),
                                 __fmul_rn(dz, dz));
            float nd = fminf(dd[j], d2);
            dd[j] = nd;
            unsigned u = __float_as_uint(nd);   // nd >= 0 -> monotonic bits
            int idx = t + j * 1024;             // ascending within thread
            if (u > bvu || (u == bvu && idx < bi)) { bvu = u; bi = idx; }
        }
        unsigned rv = __reduce_max_sync(0xffffffffu, bvu);
        int      ri = __reduce_min_sync(0xffffffffu, (bvu == rv) ? bi : 0x7fffffff);
        if (lane == 0) { pv[pr][warp] = rv; pi[pr][warp] = ri; }
        __syncthreads();

        unsigned v  = pv[pr][lane];
        int      ii = pi[pr][lane];
        unsigned mv = __reduce_max_sync(0xffffffffu, v);
        far         = __reduce_min_sync(0xffffffffu, (v == mv) ? ii : 0x7fffffff);

        if (t == 0) {
            float* o = newxyz + (size_t)(b * S_ + it) * 3;
            o[0] = sx[far]; o[1] = sy[far]; o[2] = sz[far];
        }
    }
}

// ============================================================================
// 2) KNN — 2-level radix select; 16 queries/block from smem-resident xyz
// ============================================================================
__device__ __forceinline__ void scan_select(const unsigned* hist, unsigned NEED,
                                            unsigned* out_c, unsigned* out_r, int t)
{
    if (t < 32) {
        unsigned acc[8]; unsigned tl = 0;
#pragma unroll
        for (int j = 0; j < 8; j++) { acc[j] = hist[t * 8 + j]; tl += acc[j]; }
        unsigned run = tl;
#pragma unroll
        for (int off = 1; off < 32; off <<= 1) {
            unsigned n = __shfl_up_sync(0xffffffffu, run, off);
            if (t >= off) run += n;
        }
        unsigned excl = run - tl;
        if (excl < NEED && NEED <= run) {
            unsigned c = excl;
#pragma unroll
            for (int j = 0; j < 8; j++) {
                if (c + acc[j] >= NEED) { *out_c = t * 8 + j; *out_r = NEED - c; break; }
                c += acc[j];
            }
        }
    }
}

#define NCAND 256

__global__ void __launch_bounds__(256) knn_kernel(const float* __restrict__ xyz,
                                                  const float* __restrict__ newxyz)
{
    extern __shared__ float sm[];
    float*    sx   = sm;
    float*    sy   = sm + N_;
    float*    sz   = sm + 2 * N_;
    unsigned* du   = (unsigned*)(sm + 3 * N_);
    unsigned* hist = du + N_;
    unsigned long long* cand = (unsigned long long*)(hist + 256);
    __shared__ unsigned s_c1, s_need1, s_c2, s_need2, s_cnt, s_ccnt;

    const int t = threadIdx.x;
    const int qbase = blockIdx.x * 16;
    const int b = qbase >> 10;

    const float* bp = xyz + (size_t)b * N_ * 3;
    for (int i = t; i < N_ * 3; i += 256) {
        float v = bp[i];
        int p = i / 3, c = i - 3 * p;
        (c == 0 ? sx : (c == 1 ? sy : sz))[p] = v;
    }
    __syncthreads();

    for (int q = 0; q < 16; q++) {
        const int row = qbase + q;
        const float qx = newxyz[row * 3 + 0];
        const float qy = newxyz[row * 3 + 1];
        const float qz = newxyz[row * 3 + 2];
        const float a2 = __fadd_rn(__fadd_rn(__fmul_rn(qx, qx), __fmul_rn(qy, qy)),
                                   __fmul_rn(qz, qz));

        hist[t] = 0;
        if (t == 0) { s_cnt = 0; s_ccnt = 0; }
        __syncthreads();

        for (int i = t; i < N_; i += 256) {
            float x = sx[i], y = sy[i], z = sz[i];
            float b2 = __fadd_rn(__fadd_rn(__fmul_rn(x, x), __fmul_rn(y, y)),
                                 __fmul_rn(z, z));
            float ab = __fadd_rn(__fadd_rn(__fmul_rn(qx, x), __fmul_rn(qy, y)),
                                 __fmul_rn(qz, z));
            float d2 = fmaxf(__fadd_rn(__fsub_rn(a2, __fmul_rn(2.0f, ab)), b2), 0.0f);
            unsigned u = __float_as_uint(d2);
            du[i] = u;
            atomicAdd(&hist[u >> 24], 1u);
        }
        __syncthreads();

        scan_select(hist, K_, &s_c1, &s_need1, t);
        __syncthreads();
        const unsigned c1 = s_c1, need1 = s_need1;

        hist[t] = 0;
        __syncthreads();
        for (int i = t; i < N_; i += 256) {
            unsigned u = du[i];
            if ((u >> 24) == c1) atomicAdd(&hist[(u >> 16) & 255u], 1u);
        }
        __syncthreads();

        scan_select(hist, need1, &s_c2, &s_need2, t);
        __syncthreads();
        const unsigned thr16 = (c1 << 8) | s_c2;
        const unsigned need2 = s_need2;

        for (int i = t; i < N_; i += 256) {
            unsigned u = du[i];
            unsigned k16 = u >> 16;
            if (k16 < thr16) {
                unsigned p = atomicAdd(&s_cnt, 1u);
                g_knn[(size_t)row * K_ + p] = i;
            } else if (k16 == thr16) {
                unsigned c = atomicAdd(&s_ccnt, 1u);
                if (c < NCAND) cand[c] = (((unsigned long long)u) << 12) | (unsigned)i;
            }
        }
        __syncthreads();

        if (t == 0) {
            int baseo = (int)s_cnt;
            int nc = (int)(s_ccnt < (unsigned)NCAND ? s_ccnt : (unsigned)NCAND);
            for (int j = 0; j < (int)need2; j++) {
                unsigned long long best = ~0ULL; int bj = 0;
                for (int m = 0; m < nc; m++)
                    if (cand[m] < best) { best = cand[m]; bj = m; }
                g_knn[(size_t)row * K_ + baseo + j] = (int)(best & 0xFFFu);
                cand[bj] = ~0ULL;
            }
        }
        __syncthreads();
    }
}

// ============================================================================
// 3a) Precompute  g_fW0 = features @ W0[3:67]   (f32x2)
// ============================================================================
__global__ void __launch_bounds__(128) pre_kernel(const float* __restrict__ feat,
                                                  const float* __restrict__ W0,
                                                  float* __restrict__ out)
{
    __shared__ float Wf[64 * 64];
    __shared__ float R[32 * 68];
    const int t = threadIdx.x;
    const int base = blockIdx.x * 32;

    for (int i = t; i < 64 * 64; i += 128) Wf[i] = W0[192 + i];
    {
        const int k = t >> 2, l = t & 3;
        const float* fr = feat + (size_t)(base + k) * 64;
        float* dst = R + k * 68;
#pragma unroll
        for (int j = 0; j < 4; j++) {
            float4 v = *(const float4*)(fr + (l + 4 * j) * 4);
            float* d = dst + (l + 4 * j) * 4;
            d[0] = v.x; d[1] = v.y; d[2] = v.z; d[3] = v.w;
        }
    }
    __syncthreads();

    const int kp = t >> 3, cg = t & 7, co0 = cg * 8;
    const float* in0 = R + kp * 68;
    const float* in1 = R + (kp + 16) * 68;
    unsigned long long acc0[4] = {0, 0, 0, 0}, acc1[4] = {0, 0, 0, 0};
#pragma unroll 4
    for (int ci = 0; ci < 64; ci++) {
        unsigned long long a0 = pack2(in0[ci]);
        unsigned long long a1 = pack2(in1[ci]);
        const ulonglong2* wr = (const ulonglong2*)(Wf + ci * 64 + co0);
        ulonglong2 w0 = wr[0], w1 = wr[1];
        fma2(acc0[0], a0, w0.x); fma2(acc1[0], a1, w0.x);
        fma2(acc0[1], a0, w0.y); fma2(acc1[1], a1, w0.y);
        fma2(acc0[2], a0, w1.x); fma2(acc1[2], a1, w1.x);
        fma2(acc0[3], a0, w1.y); fma2(acc1[3], a1, w1.y);
    }
    float2* o0 = (float2*)(out + (size_t)(base + kp) * 64 + co0);
    float2* o1 = (float2*)(out + (size_t)(base + kp + 16) * 64 + co0);
#pragma unroll
    for (int p = 0; p < 4; p++) { o0[p] = unpack2(acc0[p]); o1[p] = unpack2(acc1[p]); }
}

// ============================================================================
// 3b) Fused gather + MLP (f32x2) + max-pool.  One 128-thr block per (b,s).
// ============================================================================
template <int COUT>
__device__ __forceinline__ void layer64(
    const float* inb, int sin, float* outb, int sout,
    const float* __restrict__ Wg, const float* __restrict__ bg,
    const float* __restrict__ gg, const float* __restrict__ beg,
    const float* __restrict__ mg, const float* __restrict__ vg,
    float* Wsm, float* bnsm, int t)
{
    __syncthreads();
    for (int i = t; i < 64 * COUT; i += 128) Wsm[i] = Wg[i];
    if (t < COUT) {
        float sc = gg[t] * rsqrtf(vg[t] + 1e-3f);
        bnsm[t]            = sc;
        bnsm[COUT + t]     = beg[t] - mg[t] * sc;
        bnsm[2 * COUT + t] = bg[t];
    }
    __syncthreads();

    constexpr int CO = COUT / 8;
    constexpr int NP = CO / 2;
    const int kp = t >> 3, cg = t & 7, co0 = cg * CO;
    const float* in0 = inb + kp * sin;
    const float* in1 = inb + (kp + 16) * sin;

    unsigned long long acc0[NP], acc1[NP];
#pragma unroll
    for (int p = 0; p < NP; p++) { acc0[p] = 0; acc1[p] = 0; }

#pragma unroll 4
    for (int ci = 0; ci < 64; ci++) {
        unsigned long long a0 = pack2(in0[ci]);
        unsigned long long a1 = pack2(in1[ci]);
        const ulonglong2* wr = (const ulonglong2*)(Wsm + ci * COUT + co0);
#pragma unroll
        for (int u = 0; u < NP / 2; u++) {
            ulonglong2 w = wr[u];
            fma2(acc0[2 * u],     a0, w.x); fma2(acc1[2 * u],     a1, w.x);
            fma2(acc0[2 * u + 1], a0, w.y); fma2(acc1[2 * u + 1], a1, w.y);
        }
    }

    float* o0 = outb + kp * sout + co0;
    float* o1 = outb + (kp + 16) * sout + co0;
#pragma unroll
    for (int p = 0; p < NP; p++) {
        float2 v0 = unpack2(acc0[p]), v1 = unpack2(acc1[p]);
        int ca = co0 + 2 * p, cb = ca + 1;
        o0[2 * p]     = fmaxf(v0.x + bnsm[2 * COUT + ca], 0.0f) * bnsm[ca] + bnsm[COUT + ca];
        o0[2 * p + 1] = fmaxf(v0.y + bnsm[2 * COUT + cb], 0.0f) * bnsm[cb] + bnsm[COUT + cb];
        o1[2 * p]     = fmaxf(v1.x + bnsm[2 * COUT + ca], 0.0f) * bnsm[ca] + bnsm[COUT + ca];
        o1[2 * p + 1] = fmaxf(v1.y + bnsm[2 * COUT + cb], 0.0f) * bnsm[cb] + bnsm[COUT + cb];
    }
}

__global__ void __launch_bounds__(128) mlp_kernel(
    const float* __restrict__ xyz, const float* __restrict__ newxyz,
    const float* __restrict__ fW0,
    const float* __restrict__ W0, const float* __restrict__ b0,
    const float* __restrict__ g0, const float* __restrict__ be0,
    const float* __restrict__ m0, const float* __restrict__ v0,
    const float* __restrict__ W1, const float* __restrict__ b1,
    const float* __restrict__ g1, const float* __restrict__ be1,
    const float* __restrict__ m1, const float* __restrict__ v1,
    const float* __restrict__ W2, const float* __restrict__ b2,
    const float* __restrict__ g2, const float* __restrict__ be2,
    const float* __restrict__ m2, const float* __restrict__ v2,
    float* __restrict__ outp)
{
    extern __shared__ float sm[];
    float* bufG = sm;                 // 32*64  = 2048 fl
    float* gx   = bufG + 2048;        // 32*4   = 128
    float* bufX = gx + 128;           // 32*68  = 2176
    float* bufY = bufX + 2176;        // 32*68  = 2176
    float* Wsm  = bufY + 2176;        // 64*128 = 8192
    float* bnsm = Wsm + 8192;         // 3*128  = 384
    float* bufZ = sm;                 // 32*132 = 4224 fl, aliases bufG|gx|bufX (dead at L2)
    __shared__ int   sidx[K_];
    __shared__ float q[3];

    const int t = threadIdx.x;
    const int row = blockIdx.x;
    const int b = row >> 10;

    if (t < K_) sidx[t] = g_knn[(size_t)row * K_ + t];
    if (t < 3)  q[t] = newxyz[row * 3 + t];
    __syncthreads();

    {
        const int k = t >> 2, l = t & 3;
        const int id = sidx[k];
        const float* fr = fW0 + ((size_t)(b * N_) + id) * 64;
        float* dst = bufG + k * 64;
        if (l == 0) {
            const float* xr = xyz + ((size_t)(b * N_) + id) * 3;
            gx[k * 4 + 0] = __fsub_rn(xr[0], q[0]);
            gx[k * 4 + 1] = __fsub_rn(xr[1], q[1]);
            gx[k * 4 + 2] = __fsub_rn(xr[2], q[2]);
        }
#pragma unroll
        for (int j = 0; j < 4; j++) {
            float4 v = *(const float4*)(fr + (l + 4 * j) * 4);
            float* d = dst + (l + 4 * j) * 4;
            d[0] = v.x; d[1] = v.y; d[2] = v.z; d[3] = v.w;
        }
    }

    // ---- layer 0: xyz part (3 ci) + precomputed feature part ----
    {
        __syncthreads();
        for (int i = t; i < 192; i += 128) Wsm[i] = W0[i];   // FIX: full 3x64 rows
        if (t < 64) {
            float sc = g0[t] * rsqrtf(v0[t] + 1e-3f);
            bnsm[t]       = sc;
            bnsm[64 + t]  = be0[t] - m0[t] * sc;
            bnsm[128 + t] = b0[t];
        }
        __syncthreads();

        const int kp = t >> 3, cg = t & 7, co0 = cg * 8;
        const ulonglong2* gA = (const ulonglong2*)(bufG + kp * 64 + co0);
        const ulonglong2* gB = (const ulonglong2*)(bufG + (kp + 16) * 64 + co0);
        ulonglong2 ga0 = gA[0], ga1 = gA[1], gb0 = gB[0], gb1 = gB[1];
        unsigned long long acc0[4] = {ga0.x, ga0.y, ga1.x, ga1.y};
        unsigned long long acc1[4] = {gb0.x, gb0.y, gb1.x, gb1.y};
#pragma unroll
        for (int ci = 0; ci < 3; ci++) {
            unsigned long long a0 = pack2(gx[kp * 4 + ci]);
            unsigned long long a1 = pack2(gx[(kp + 16) * 4 + ci]);
            const ulonglong2* wr = (const ulonglong2*)(Wsm + ci * 64 + co0);
            ulonglong2 w0 = wr[0], w1 = wr[1];
            fma2(acc0[0], a0, w0.x); fma2(acc1[0], a1, w0.x);
            fma2(acc0[1], a0, w0.y); fma2(acc1[1], a1, w0.y);
            fma2(acc0[2], a0, w1.x); fma2(acc1[2], a1, w1.x);
            fma2(acc0[3], a0, w1.y); fma2(acc1[3], a1, w1.y);
        }
        float* o0 = bufX + kp * 68 + co0;
        float* o1 = bufX + (kp + 16) * 68 + co0;
#pragma unroll
        for (int p = 0; p < 4; p++) {
            float2 v0p = unpack2(acc0[p]), v1p = unpack2(acc1[p]);
            int ca = co0 + 2 * p, cb = ca + 1;
            o0[2 * p]     = fmaxf(v0p.x + bnsm[128 + ca], 0.0f) * bnsm[ca] + bnsm[64 + ca];
            o0[2 * p + 1] = fmaxf(v0p.y + bnsm[128 + cb], 0.0f) * bnsm[cb] + bnsm[64 + cb];
            o1[2 * p]     = fmaxf(v1p.x + bnsm[128 + ca], 0.0f) * bnsm[ca] + bnsm[64 + ca];
            o1[2 * p + 1] = fmaxf(v1p.y + bnsm[128 + cb], 0.0f) * bnsm[cb] + bnsm[64 + cb];
        }
    }

    layer64<64 >(bufX, 68, bufY, 68,  W1, b1, g1, be1, m1, v1, Wsm, bnsm, t);
    layer64<128>(bufY, 68, bufZ, 132, W2, b2, g2, be2, m2, v2, Wsm, bnsm, t);
    __syncthreads();

    {
        float m = -CUDART_INF_F;
#pragma unroll
        for (int k = 0; k < K_; k++) m = fmaxf(m, bufZ[k * 132 + t]);
        outp[(size_t)row * 128 + t] = m;
    }
}

// ============================================================================
extern "C" void kernel_launch(void* const* d_in, const int* in_sizes, int n_in,
                              void* d_out, int out_size)
{
    (void)in_sizes; (void)n_in; (void)out_size;
    const float* xyz  = (const float*)d_in[0];
    const float* feat = (const float*)d_in[1];
    const float* P[18];
    for (int i = 0; i < 18; i++) P[i] = (const float*)d_in[2 + i];

    float* out    = (float*)d_out;
    float* newxyz = out;
    float* pooled = out + (size_t)B_ * S_ * 3;

    float* fW0;
    cudaGetSymbolAddress((void**)&fW0, g_fW0);

    const int fps_smem = 3 * N_ * 4;                               // 49152
    const int knn_smem = (3 * N_ + N_ + 256) * 4 + NCAND * 8;       // 68608
    const int mlp_smem = (2048 + 128 + 2176 + 2176 + 8192 + 384) * 4; // 60416

    cudaFuncSetAttribute(fps_kernel, cudaFuncAttributeMaxDynamicSharedMemorySize, fps_smem);
    cudaFuncSetAttribute(knn_kernel, cudaFuncAttributeMaxDynamicSharedMemorySize, knn_smem);
    cudaFuncSetAttribute(mlp_kernel, cudaFuncAttributeMaxDynamicSharedMemorySize, mlp_smem);

    pre_kernel<<<B_ * N_ / 32, 128>>>(feat, P[0], fW0);
    fps_kernel<<<B_, 1024, fps_smem>>>(xyz, newxyz);
    knn_kernel<<<B_ * S_ / 16, 256, knn_smem>>>(xyz, newxyz);
    mlp_kernel<<<B_ * S_, 128, mlp_smem>>>(
        xyz, newxyz, fW0,
        P[0],  P[1],  P[2],  P[3],  P[4],  P[5],
        P[6],  P[7],  P[8],  P[9],  P[10], P[11],
        P[12], P[13], P[14], P[15], P[16], P[17],
        pooled);
}

// round 4
// speedup vs baseline: 1.5057x; 1.0098x over previous
#include <cuda_runtime.h>
#include <math_constants.h>
#include <cstddef>

#define B_   16
#define N_   4096
#define S_   1024
#define K_   32
#define CF_  64

// device scratch (no allocation allowed)
__device__ int   g_knn[B_ * S_ * K_];
__device__ float g_fW0[B_ * N_ * 64];     // feat @ W0[3:67]  (16 MB)

// ---------------------------------------------------------------- f32x2 helpers
__device__ __forceinline__ unsigned long long pack2(float a) {
    unsigned long long r;
    asm("mov.b64 %0, {%1, %1};" : "=l"(r) : "f"(a));
    return r;
}
__device__ __forceinline__ void fma2(unsigned long long& d,
                                     unsigned long long a, unsigned long long b) {
    asm("fma.rn.f32x2 %0, %1, %2, %0;" : "+l"(d) : "l"(a), "l"(b));
}
__device__ __forceinline__ float2 unpack2(unsigned long long v) {
    float2 f;
    asm("mov.b64 {%0, %1}, %2;" : "=f"(f.x), "=f"(f.y) : "l"(v));
    return f;
}

// ============================================================================
// 1) FPS — one block/batch, 1024 thr, REDUX reductions, single barrier/iter
// ============================================================================
__global__ void __launch_bounds__(1024) fps_kernel(const float* __restrict__ xyz,
                                                   float* __restrict__ newxyz)
{
    extern __shared__ float sm[];
    float* sx = sm;
    float* sy = sm + N_;
    float* sz = sm + 2 * N_;
    __shared__ unsigned pv[2][32];
    __shared__ int      pi[2][32];

    const int b = blockIdx.x;
    const int t = threadIdx.x;
    const int lane = t & 31, warp = t >> 5;
    const float* base = xyz + (size_t)b * N_ * 3;

    float px[4], py[4], pz[4], dd[4];
#pragma unroll
    for (int j = 0; j < 4; j++) {
        int p = t + j * 1024;
        float x = base[3 * p + 0], y = base[3 * p + 1], z = base[3 * p + 2];
        px[j] = x; py[j] = y; pz[j] = z;
        sx[p] = x; sy[p] = y; sz[p] = z;
        dd[j] = 1e10f;
    }
    __syncthreads();

    int far = 0;
    for (int it = 0; it < S_; it++) {
        const int pr = it & 1;
        const float cx = sx[far], cy = sy[far], cz = sz[far];

        unsigned bvu = 0u;
        int      bi  = 0x7fffffff;
#pragma unroll
        for (int j = 0; j < 4; j++) {
            float dx = __fsub_rn(px[j], cx);
            float dy = __fsub_rn(py[j], cy);
            float dz = __fsub_rn(pz[j], cz);
            float d2 = __fadd_rn(__fadd_rn(__fmul_rn(dx, dx), __fmul_rn(dy, dy)),
                                 __fmul_rn(dz, dz));
            float nd = fminf(dd[j], d2);
            dd[j] = nd;
            unsigned u = __float_as_uint(nd);   // nd >= 0 -> monotonic bits
            int idx = t + j * 1024;             // ascending within thread
            if (u > bvu || (u == bvu && idx < bi)) { bvu = u; bi = idx; }
        }
        unsigned rv = __reduce_max_sync(0xffffffffu, bvu);
        int      ri = __reduce_min_sync(0xffffffffu, (bvu == rv) ? bi : 0x7fffffff);
        if (lane == 0) { pv[pr][warp] = rv; pi[pr][warp] = ri; }
        __syncthreads();

        unsigned v  = pv[pr][lane];
        int      ii = pi[pr][lane];
        unsigned mv = __reduce_max_sync(0xffffffffu, v);
        far         = __reduce_min_sync(0xffffffffu, (v == mv) ? ii : 0x7fffffff);

        if (t == 0) {
            float* o = newxyz + (size_t)(b * S_ + it) * 3;
            o[0] = sx[far]; o[1] = sy[far]; o[2] = sz[far];
        }
    }
}

// ============================================================================
// 2) KNN — 2-level radix select; 16 queries/block from smem-resident xyz
// ============================================================================
__device__ __forceinline__ void scan_select(const unsigned* hist, unsigned NEED,
                                            unsigned* out_c, unsigned* out_r, int t)
{
    if (t < 32) {
        unsigned acc[8]; unsigned tl = 0;
#pragma unroll
        for (int j = 0; j < 8; j++) { acc[j] = hist[t * 8 + j]; tl += acc[j]; }
        unsigned run = tl;
#pragma unroll
        for (int off = 1; off < 32; off <<= 1) {
            unsigned n = __shfl_up_sync(0xffffffffu, run, off);
            if (t >= off) run += n;
        }
        unsigned excl = run - tl;
        if (excl < NEED && NEED <= run) {
            unsigned c = excl;
#pragma unroll
            for (int j = 0; j < 8; j++) {
                if (c + acc[j] >= NEED) { *out_c = t * 8 + j; *out_r = NEED - c; break; }
                c += acc[j];
            }
        }
    }
}

#define NCAND 256

__global__ void __launch_bounds__(256) knn_kernel(const float* __restrict__ xyz,
                                                  const float* __restrict__ newxyz)
{
    extern __shared__ float sm[];
    float*    sx   = sm;
    float*    sy   = sm + N_;
    float*    sz   = sm + 2 * N_;
    unsigned* du   = (unsigned*)(sm + 3 * N_);
    unsigned* hist = du + N_;
    unsigned long long* cand = (unsigned long long*)(hist + 256);
    __shared__ unsigned s_c1, s_need1, s_c2, s_need2, s_cnt, s_ccnt;

    const int t = threadIdx.x;
    const int qbase = blockIdx.x * 16;
    const int b = qbase >> 10;

    const float* bp = xyz + (size_t)b * N_ * 3;
    for (int i = t; i < N_ * 3; i += 256) {
        float v = bp[i];
        int p = i / 3, c = i - 3 * p;
        (c == 0 ? sx : (c == 1 ? sy : sz))[p] = v;
    }
    __syncthreads();

    for (int q = 0; q < 16; q++) {
        const int row = qbase + q;
        const float qx = newxyz[row * 3 + 0];
        const float qy = newxyz[row * 3 + 1];
        const float qz = newxyz[row * 3 + 2];
        const float a2 = __fadd_rn(__fadd_rn(__fmul_rn(qx, qx), __fmul_rn(qy, qy)),
                                   __fmul_rn(qz, qz));

        hist[t] = 0;
        if (t == 0) { s_cnt = 0; s_ccnt = 0; }
        __syncthreads();

        for (int i = t; i < N_; i += 256) {
            float x = sx[i], y = sy[i], z = sz[i];
            float b2 = __fadd_rn(__fadd_rn(__fmul_rn(x, x), __fmul_rn(y, y)),
                                 __fmul_rn(z, z));
            float ab = __fadd_rn(__fadd_rn(__fmul_rn(qx, x), __fmul_rn(qy, y)),
                                 __fmul_rn(qz, z));
            float d2 = fmaxf(__fadd_rn(__fsub_rn(a2, __fmul_rn(2.0f, ab)), b2), 0.0f);
            unsigned u = __float_as_uint(d2);
            du[i] = u;
            atomicAdd(&hist[u >> 24], 1u);
        }
        __syncthreads();

        scan_select(hist, K_, &s_c1, &s_need1, t);
        __syncthreads();
        const unsigned c1 = s_c1, need1 = s_need1;

        hist[t] = 0;
        __syncthreads();
        for (int i = t; i < N_; i += 256) {
            unsigned u = du[i];
            if ((u >> 24) == c1) atomicAdd(&hist[(u >> 16) & 255u], 1u);
        }
        __syncthreads();

        scan_select(hist, need1, &s_c2, &s_need2, t);
        __syncthreads();
        const unsigned thr16 = (c1 << 8) | s_c2;
        const unsigned need2 = s_need2;

        for (int i = t; i < N_; i += 256) {
            unsigned u = du[i];
            unsigned k16 = u >> 16;
            if (k16 < thr16) {
                unsigned p = atomicAdd(&s_cnt, 1u);
                g_knn[(size_t)row * K_ + p] = i;
            } else if (k16 == thr16) {
                unsigned c = atomicAdd(&s_ccnt, 1u);
                if (c < NCAND) cand[c] = (((unsigned long long)u) << 12) | (unsigned)i;
            }
        }
        __syncthreads();

        if (t == 0) {
            int baseo = (int)s_cnt;
            int nc = (int)(s_ccnt < (unsigned)NCAND ? s_ccnt : (unsigned)NCAND);
            for (int j = 0; j < (int)need2; j++) {
                unsigned long long best = ~0ULL; int bj = 0;
                for (int m = 0; m < nc; m++)
                    if (cand[m] < best) { best = cand[m]; bj = m; }
                g_knn[(size_t)row * K_ + baseo + j] = (int)(best & 0xFFFu);
                cand[bj] = ~0ULL;
            }
        }
        __syncthreads();
    }
}

// ============================================================================
// 3a) Precompute  g_fW0 = features @ W0[3:67]   (f32x2)
// ============================================================================
__global__ void __launch_bounds__(128) pre_kernel(const float* __restrict__ feat,
                                                  const float* __restrict__ W0,
                                                  float* __restrict__ out)
{
    __shared__ float Wf[64 * 64];
    __shared__ float R[32 * 68];
    const int t = threadIdx.x;
    const int base = blockIdx.x * 32;

    for (int i = t; i < 64 * 64; i += 128) Wf[i] = W0[192 + i];
    {
        const int k = t >> 2, l = t & 3;
        const float* fr = feat + (size_t)(base + k) * 64;
        float* dst = R + k * 68;
#pragma unroll
        for (int j = 0; j < 4; j++) {
            float4 v = *(const float4*)(fr + (l + 4 * j) * 4);
            float* d = dst + (l + 4 * j) * 4;
            d[0] = v.x; d[1] = v.y; d[2] = v.z; d[3] = v.w;
        }
    }
    __syncthreads();

    const int kp = t >> 3, cg = t & 7, co0 = cg * 8;
    const float* in0 = R + kp * 68;
    const float* in1 = R + (kp + 16) * 68;
    unsigned long long acc0[4] = {0, 0, 0, 0}, acc1[4] = {0, 0, 0, 0};
#pragma unroll 4
    for (int ci = 0; ci < 64; ci++) {
        unsigned long long a0 = pack2(in0[ci]);
        unsigned long long a1 = pack2(in1[ci]);
        const ulonglong2* wr = (const ulonglong2*)(Wf + ci * 64 + co0);
        ulonglong2 w0 = wr[0], w1 = wr[1];
        fma2(acc0[0], a0, w0.x); fma2(acc1[0], a1, w0.x);
        fma2(acc0[1], a0, w0.y); fma2(acc1[1], a1, w0.y);
        fma2(acc0[2], a0, w1.x); fma2(acc1[2], a1, w1.x);
        fma2(acc0[3], a0, w1.y); fma2(acc1[3], a1, w1.y);
    }
    float2* o0 = (float2*)(out + (size_t)(base + kp) * 64 + co0);
    float2* o1 = (float2*)(out + (size_t)(base + kp + 16) * 64 + co0);
#pragma unroll
    for (int p = 0; p < 4; p++) { o0[p] = unpack2(acc0[p]); o1[p] = unpack2(acc1[p]); }
}

// ============================================================================
// 3b) MLP: weights staged ONCE per block; 256 thr = 2 independent halves,
//     each half processes 8 of the block's 16 (b,s) rows.
// ============================================================================
template <int COUT>
__device__ __forceinline__ void layer_sm(
    const float* inb, int sin, float* outb, int sout,
    const float* Wsm, const float* bnsm, int tt)
{
    constexpr int CO = COUT / 8;
    constexpr int NP = CO / 2;
    const int kp = tt >> 3, cg = tt & 7, co0 = cg * CO;
    const float* in0 = inb + kp * sin;
    const float* in1 = inb + (kp + 16) * sin;

    unsigned long long acc0[NP], acc1[NP];
#pragma unroll
    for (int p = 0; p < NP; p++) { acc0[p] = 0; acc1[p] = 0; }

#pragma unroll 4
    for (int ci = 0; ci < 64; ci++) {
        unsigned long long a0 = pack2(in0[ci]);
        unsigned long long a1 = pack2(in1[ci]);
        const ulonglong2* wr = (const ulonglong2*)(Wsm + ci * COUT + co0);
#pragma unroll
        for (int u = 0; u < NP / 2; u++) {
            ulonglong2 w = wr[u];
            fma2(acc0[2 * u],     a0, w.x); fma2(acc1[2 * u],     a1, w.x);
            fma2(acc0[2 * u + 1], a0, w.y); fma2(acc1[2 * u + 1], a1, w.y);
        }
    }

    float* o0 = outb + kp * sout + co0;
    float* o1 = outb + (kp + 16) * sout + co0;
#pragma unroll
    for (int p = 0; p < NP; p++) {
        float2 v0 = unpack2(acc0[p]), v1 = unpack2(acc1[p]);
        int ca = co0 + 2 * p, cb = ca + 1;
        o0[2 * p]     = fmaxf(v0.x + bnsm[2 * COUT + ca], 0.0f) * bnsm[ca] + bnsm[COUT + ca];
        o0[2 * p + 1] = fmaxf(v0.y + bnsm[2 * COUT + cb], 0.0f) * bnsm[cb] + bnsm[COUT + cb];
        o1[2 * p]     = fmaxf(v1.x + bnsm[2 * COUT + ca], 0.0f) * bnsm[ca] + bnsm[COUT + ca];
        o1[2 * p + 1] = fmaxf(v1.y + bnsm[2 * COUT + cb], 0.0f) * bnsm[cb] + bnsm[COUT + cb];
    }
}

// smem layout (floats):
//   0     W0s   [192]
//   192   bn0   [192]
//   384   W1s   [4096]
//   4480  bn1   [192]
//   4672  W2s   [8192]
//   12864 bn2   [384]
//   13248 areaA [2 x 4352]  (per half: bufG 2048 | gx 128 | bufX 2176; bufZ aliases)
//   21952 bufY  [2 x 2176]
#define MLP_SMEM_FL (13248 + 2 * 4352 + 2 * 2176)

__global__ void __launch_bounds__(256) mlp_kernel(
    const float* __restrict__ xyz, const float* __restrict__ newxyz,
    const float* __restrict__ fW0,
    const float* __restrict__ W0, const float* __restrict__ b0,
    const float* __restrict__ g0, const float* __restrict__ be0,
    const float* __restrict__ m0, const float* __restrict__ v0,
    const float* __restrict__ W1, const float* __restrict__ b1,
    const float* __restrict__ g1, const float* __restrict__ be1,
    const float* __restrict__ m1, const float* __restrict__ v1,
    const float* __restrict__ W2, const float* __restrict__ b2,
    const float* __restrict__ g2, const float* __restrict__ be2,
    const float* __restrict__ m2, const float* __restrict__ v2,
    float* __restrict__ outp)
{
    extern __shared__ float sm[];
    float* W0s = sm;
    float* bn0 = sm + 192;
    float* W1s = sm + 384;
    float* bn1 = sm + 4480;
    float* W2s = sm + 4672;
    float* bn2 = sm + 12864;
    __shared__ int   sidx[16 * K_];
    __shared__ float qv[16 * 3];

    const int t  = threadIdx.x;
    const int sub = t >> 7;            // half id: 0 or 1
    const int tt  = t & 127;           // thread within half
    const int qbase = blockIdx.x * 16;
    const int b = qbase >> 10;

    float* areaA = sm + 13248 + sub * 4352;
    float* bufG  = areaA;              // 32*64
    float* gx    = areaA + 2048;       // 32*4
    float* bufX  = areaA + 2176;       // 32*68
    float* bufZ  = areaA;              // 32*132 (aliases bufG|gx|bufX, dead then)
    float* bufY  = sm + 21952 + sub * 2176;   // 32*68

    // ---- stage weights + BN constants + indices once per block ----
    for (int i = t; i < 192;  i += 256) W0s[i] = W0[i];
    for (int i = t; i < 4096; i += 256) W1s[i] = W1[i];
    for (int i = t; i < 8192; i += 256) W2s[i] = W2[i];
    if (t < 64) {
        float s0 = g0[t] * rsqrtf(v0[t] + 1e-3f);
        bn0[t] = s0; bn0[64 + t] = be0[t] - m0[t] * s0; bn0[128 + t] = b0[t];
        float s1 = g1[t] * rsqrtf(v1[t] + 1e-3f);
        bn1[t] = s1; bn1[64 + t] = be1[t] - m1[t] * s1; bn1[128 + t] = b1[t];
    }
    if (t < 128) {
        float s2 = g2[t] * rsqrtf(v2[t] + 1e-3f);
        bn2[t] = s2; bn2[128 + t] = be2[t] - m2[t] * s2; bn2[256 + t] = b2[t];
    }
    for (int i = t; i < 16 * K_; i += 256) sidx[i] = g_knn[(size_t)qbase * K_ + i];
    if (t < 48) qv[t] = newxyz[qbase * 3 + t];
    __syncthreads();

    for (int j = 0; j < 8; j++) {
        const int q   = sub * 8 + j;
        const int row = qbase + q;
        const int* si = sidx + q * K_;

        // gather [fW0(64) | grouped_xyz(3)]: 4 threads per k
        {
            const int k = tt >> 2, l = tt & 3;
            const int id = si[k];
            const float* fr = fW0 + ((size_t)(b * N_) + id) * 64;
            float* dst = bufG + k * 64;
            if (l == 0) {
                const float* xr = xyz + ((size_t)(b * N_) + id) * 3;
                gx[k * 4 + 0] = __fsub_rn(xr[0], qv[q * 3 + 0]);
                gx[k * 4 + 1] = __fsub_rn(xr[1], qv[q * 3 + 1]);
                gx[k * 4 + 2] = __fsub_rn(xr[2], qv[q * 3 + 2]);
            }
#pragma unroll
            for (int jj = 0; jj < 4; jj++) {
                float4 v = *(const float4*)(fr + (l + 4 * jj) * 4);
                float* d = dst + (l + 4 * jj) * 4;
                d[0] = v.x; d[1] = v.y; d[2] = v.z; d[3] = v.w;
            }
        }
        __syncthreads();

        // ---- layer 0: 3 xyz ci + precomputed feature part ----
        {
            const int kp = tt >> 3, cg = tt & 7, co0 = cg * 8;
            const ulonglong2* gA = (const ulonglong2*)(bufG + kp * 64 + co0);
            const ulonglong2* gB = (const ulonglong2*)(bufG + (kp + 16) * 64 + co0);
            ulonglong2 ga0 = gA[0], ga1 = gA[1], gb0 = gB[0], gb1 = gB[1];
            unsigned long long acc0[4] = {ga0.x, ga0.y, ga1.x, ga1.y};
            unsigned long long acc1[4] = {gb0.x, gb0.y, gb1.x, gb1.y};
#pragma unroll
            for (int ci = 0; ci < 3; ci++) {
                unsigned long long a0 = pack2(gx[kp * 4 + ci]);
                unsigned long long a1 = pack2(gx[(kp + 16) * 4 + ci]);
                const ulonglong2* wr = (const ulonglong2*)(W0s + ci * 64 + co0);
                ulonglong2 w0 = wr[0], w1 = wr[1];
                fma2(acc0[0], a0, w0.x); fma2(acc1[0], a1, w0.x);
                fma2(acc0[1], a0, w0.y); fma2(acc1[1], a1, w0.y);
                fma2(acc0[2], a0, w1.x); fma2(acc1[2], a1, w1.x);
                fma2(acc0[3], a0, w1.y); fma2(acc1[3], a1, w1.y);
            }
            float* o0 = bufX + kp * 68 + co0;
            float* o1 = bufX + (kp + 16) * 68 + co0;
#pragma unroll
            for (int p = 0; p < 4; p++) {
                float2 v0p = unpack2(acc0[p]), v1p = unpack2(acc1[p]);
                int ca = co0 + 2 * p, cb = ca + 1;
                o0[2 * p]     = fmaxf(v0p.x + bn0[128 + ca], 0.0f) * bn0[ca] + bn0[64 + ca];
                o0[2 * p + 1] = fmaxf(v0p.y + bn0[128 + cb], 0.0f) * bn0[cb] + bn0[64 + cb];
                o1[2 * p]     = fmaxf(v1p.x + bn0[128 + ca], 0.0f) * bn0[ca] + bn0[64 + ca];
                o1[2 * p + 1] = fmaxf(v1p.y + bn0[128 + cb], 0.0f) * bn0[cb] + bn0[64 + cb];
            }
        }
        __syncthreads();

        layer_sm<64>(bufX, 68, bufY, 68, W1s, bn1, tt);
        __syncthreads();
        layer_sm<128>(bufY, 68, bufZ, 132, W2s, bn2, tt);
        __syncthreads();

        // max-pool over k (128 channels per half)
        {
            float m = -CUDART_INF_F;
#pragma unroll
            for (int k = 0; k < K_; k++) m = fmaxf(m, bufZ[k * 132 + tt]);
            outp[(size_t)row * 128 + tt] = m;
        }
        __syncthreads();   // protect areaA before next gather
    }
}

// ============================================================================
extern "C" void kernel_launch(void* const* d_in, const int* in_sizes, int n_in,
                              void* d_out, int out_size)
{
    (void)in_sizes; (void)n_in; (void)out_size;
    const float* xyz  = (const float*)d_in[0];
    const float* feat = (const float*)d_in[1];
    const float* P[18];
    for (int i = 0; i < 18; i++) P[i] = (const float*)d_in[2 + i];

    float* out    = (float*)d_out;
    float* newxyz = out;
    float* pooled = out + (size_t)B_ * S_ * 3;

    float* fW0;
    cudaGetSymbolAddress((void**)&fW0, g_fW0);

    const int fps_smem = 3 * N_ * 4;                               // 49152
    const int knn_smem = (3 * N_ + N_ + 256) * 4 + NCAND * 8;       // 68608
    const int mlp_smem = MLP_SMEM_FL * 4;                           // 105216

    cudaFuncSetAttribute(fps_kernel, cudaFuncAttributeMaxDynamicSharedMemorySize, fps_smem);
    cudaFuncSetAttribute(knn_kernel, cudaFuncAttributeMaxDynamicSharedMemorySize, knn_smem);
    cudaFuncSetAttribute(mlp_kernel, cudaFuncAttributeMaxDynamicSharedMemorySize, mlp_smem);

    pre_kernel<<<B_ * N_ / 32, 128>>>(feat, P[0], fW0);
    fps_kernel<<<B_, 1024, fps_smem>>>(xyz, newxyz);
    knn_kernel<<<B_ * S_ / 16, 256, knn_smem>>>(xyz, newxyz);
    mlp_kernel<<<B_ * S_ / 16, 256, mlp_smem>>>(
        xyz, newxyz, fW0,
        P[0],  P[1],  P[2],  P[3],  P[4],  P[5],
        P[6],  P[7],  P[8],  P[9],  P[10], P[11],
        P[12], P[13], P[14], P[15], P[16], P[17],
        pooled);
}

// round 5
// speedup vs baseline: 2.3882x; 1.5861x over previous
#include <cuda_runtime.h>
#include <math_constants.h>
#include <cstddef>

#define B_   16
#define N_   4096
#define S_   1024
#define K_   32
#define CF_  64

// device scratch (no allocation allowed)
__device__ int   g_knn[B_ * S_ * K_];
__device__ float g_fW0[B_ * N_ * 64];          // feat @ W0[3:67]  (16 MB)
__device__ float g_X2[(size_t)B_ * S_ * K_ * 64];  // layer-1 output (134 MB)

// ---------------------------------------------------------------- f32x2 helpers
__device__ __forceinline__ unsigned long long pack2(float a) {
    unsigned long long r;
    asm("mov.b64 %0, {%1, %1};" : "=l"(r) : "f"(a));
    return r;
}
__device__ __forceinline__ void fma2(unsigned long long& d,
                                     unsigned long long a, unsigned long long b) {
    asm("fma.rn.f32x2 %0, %1, %2, %0;" : "+l"(d) : "l"(a), "l"(b));
}
__device__ __forceinline__ float2 unpack2(unsigned long long v) {
    float2 f;
    asm("mov.b64 {%0, %1}, %2;" : "=f"(f.x), "=f"(f.y) : "l"(v));
    return f;
}

// ============================================================================
// 1) FPS — unchanged (bit-correct)
// ============================================================================
__global__ void __launch_bounds__(1024) fps_kernel(const float* __restrict__ xyz,
                                                   float* __restrict__ newxyz)
{
    extern __shared__ float sm[];
    float* sx = sm;
    float* sy = sm + N_;
    float* sz = sm + 2 * N_;
    __shared__ unsigned pv[2][32];
    __shared__ int      pi[2][32];

    const int b = blockIdx.x;
    const int t = threadIdx.x;
    const int lane = t & 31, warp = t >> 5;
    const float* base = xyz + (size_t)b * N_ * 3;

    float px[4], py[4], pz[4], dd[4];
#pragma unroll
    for (int j = 0; j < 4; j++) {
        int p = t + j * 1024;
        float x = base[3 * p + 0], y = base[3 * p + 1], z = base[3 * p + 2];
        px[j] = x; py[j] = y; pz[j] = z;
        sx[p] = x; sy[p] = y; sz[p] = z;
        dd[j] = 1e10f;
    }
    __syncthreads();

    int far = 0;
    for (int it = 0; it < S_; it++) {
        const int pr = it & 1;
        const float cx = sx[far], cy = sy[far], cz = sz[far];

        unsigned bvu = 0u;
        int      bi  = 0x7fffffff;
#pragma unroll
        for (int j = 0; j < 4; j++) {
            float dx = __fsub_rn(px[j], cx);
            float dy = __fsub_rn(py[j], cy);
            float dz = __fsub_rn(pz[j], cz);
            float d2 = __fadd_rn(__fadd_rn(__fmul_rn(dx, dx), __fmul_rn(dy, dy)),
                                 __fmul_rn(dz, dz));
            float nd = fminf(dd[j], d2);
            dd[j] = nd;
            unsigned u = __float_as_uint(nd);
            int idx = t + j * 1024;
            if (u > bvu || (u == bvu && idx < bi)) { bvu = u; bi = idx; }
        }
        unsigned rv = __reduce_max_sync(0xffffffffu, bvu);
        int      ri = __reduce_min_sync(0xffffffffu, (bvu == rv) ? bi : 0x7fffffff);
        if (lane == 0) { pv[pr][warp] = rv; pi[pr][warp] = ri; }
        __syncthreads();

        unsigned v  = pv[pr][lane];
        int      ii = pi[pr][lane];
        unsigned mv = __reduce_max_sync(0xffffffffu, v);
        far         = __reduce_min_sync(0xffffffffu, (v == mv) ? ii : 0x7fffffff);

        if (t == 0) {
            float* o = newxyz + (size_t)(b * S_ + it) * 3;
            o[0] = sx[far]; o[1] = sy[far]; o[2] = sz[far];
        }
    }
}

// ============================================================================
// 2) KNN — unchanged
// ============================================================================
__device__ __forceinline__ void scan_select(const unsigned* hist, unsigned NEED,
                                            unsigned* out_c, unsigned* out_r, int t)
{
    if (t < 32) {
        unsigned acc[8]; unsigned tl = 0;
#pragma unroll
        for (int j = 0; j < 8; j++) { acc[j] = hist[t * 8 + j]; tl += acc[j]; }
        unsigned run = tl;
#pragma unroll
        for (int off = 1; off < 32; off <<= 1) {
            unsigned n = __shfl_up_sync(0xffffffffu, run, off);
            if (t >= off) run += n;
        }
        unsigned excl = run - tl;
        if (excl < NEED && NEED <= run) {
            unsigned c = excl;
#pragma unroll
            for (int j = 0; j < 8; j++) {
                if (c + acc[j] >= NEED) { *out_c = t * 8 + j; *out_r = NEED - c; break; }
                c += acc[j];
            }
        }
    }
}

#define NCAND 256

__global__ void __launch_bounds__(256) knn_kernel(const float* __restrict__ xyz,
                                                  const float* __restrict__ newxyz)
{
    extern __shared__ float sm[];
    float*    sx   = sm;
    float*    sy   = sm + N_;
    float*    sz   = sm + 2 * N_;
    unsigned* du   = (unsigned*)(sm + 3 * N_);
    unsigned* hist = du + N_;
    unsigned long long* cand = (unsigned long long*)(hist + 256);
    __shared__ unsigned s_c1, s_need1, s_c2, s_need2, s_cnt, s_ccnt;

    const int t = threadIdx.x;
    const int qbase = blockIdx.x * 16;
    const int b = qbase >> 10;

    const float* bp = xyz + (size_t)b * N_ * 3;
    for (int i = t; i < N_ * 3; i += 256) {
        float v = bp[i];
        int p = i / 3, c = i - 3 * p;
        (c == 0 ? sx : (c == 1 ? sy : sz))[p] = v;
    }
    __syncthreads();

    for (int q = 0; q < 16; q++) {
        const int row = qbase + q;
        const float qx = newxyz[row * 3 + 0];
        const float qy = newxyz[row * 3 + 1];
        const float qz = newxyz[row * 3 + 2];
        const float a2 = __fadd_rn(__fadd_rn(__fmul_rn(qx, qx), __fmul_rn(qy, qy)),
                                   __fmul_rn(qz, qz));

        hist[t] = 0;
        if (t == 0) { s_cnt = 0; s_ccnt = 0; }
        __syncthreads();

        for (int i = t; i < N_; i += 256) {
            float x = sx[i], y = sy[i], z = sz[i];
            float b2 = __fadd_rn(__fadd_rn(__fmul_rn(x, x), __fmul_rn(y, y)),
                                 __fmul_rn(z, z));
            float ab = __fadd_rn(__fadd_rn(__fmul_rn(qx, x), __fmul_rn(qy, y)),
                                 __fmul_rn(qz, z));
            float d2 = fmaxf(__fadd_rn(__fsub_rn(a2, __fmul_rn(2.0f, ab)), b2), 0.0f);
            unsigned u = __float_as_uint(d2);
            du[i] = u;
            atomicAdd(&hist[u >> 24], 1u);
        }
        __syncthreads();

        scan_select(hist, K_, &s_c1, &s_need1, t);
        __syncthreads();
        const unsigned c1 = s_c1, need1 = s_need1;

        hist[t] = 0;
        __syncthreads();
        for (int i = t; i < N_; i += 256) {
            unsigned u = du[i];
            if ((u >> 24) == c1) atomicAdd(&hist[(u >> 16) & 255u], 1u);
        }
        __syncthreads();

        scan_select(hist, need1, &s_c2, &s_need2, t);
        __syncthreads();
        const unsigned thr16 = (c1 << 8) | s_c2;
        const unsigned need2 = s_need2;

        for (int i = t; i < N_; i += 256) {
            unsigned u = du[i];
            unsigned k16 = u >> 16;
            if (k16 < thr16) {
                unsigned p = atomicAdd(&s_cnt, 1u);
                g_knn[(size_t)row * K_ + p] = i;
            } else if (k16 == thr16) {
                unsigned c = atomicAdd(&s_ccnt, 1u);
                if (c < NCAND) cand[c] = (((unsigned long long)u) << 12) | (unsigned)i;
            }
        }
        __syncthreads();

        if (t == 0) {
            int baseo = (int)s_cnt;
            int nc = (int)(s_ccnt < (unsigned)NCAND ? s_ccnt : (unsigned)NCAND);
            for (int j = 0; j < (int)need2; j++) {
                unsigned long long best = ~0ULL; int bj = 0;
                for (int m = 0; m < nc; m++)
                    if (cand[m] < best) { best = cand[m]; bj = m; }
                g_knn[(size_t)row * K_ + baseo + j] = (int)(best & 0xFFFu);
                cand[bj] = ~0ULL;
            }
        }
        __syncthreads();
    }
}

// ============================================================================
// 3a) Precompute  g_fW0 = features @ W0[3:67]   — unchanged
// ============================================================================
__global__ void __launch_bounds__(128) pre_kernel(const float* __restrict__ feat,
                                                  const float* __restrict__ W0,
                                                  float* __restrict__ out)
{
    __shared__ float Wf[64 * 64];
    __shared__ float R[32 * 68];
    const int t = threadIdx.x;
    const int base = blockIdx.x * 32;

    for (int i = t; i < 64 * 64; i += 128) Wf[i] = W0[192 + i];
    {
        const int k = t >> 2, l = t & 3;
        const float* fr = feat + (size_t)(base + k) * 64;
        float* dst = R + k * 68;
#pragma unroll
        for (int j = 0; j < 4; j++) {
            float4 v = *(const float4*)(fr + (l + 4 * j) * 4);
            float* d = dst + (l + 4 * j) * 4;
            d[0] = v.x; d[1] = v.y; d[2] = v.z; d[3] = v.w;
        }
    }
    __syncthreads();

    const int kp = t >> 3, cg = t & 7, co0 = cg * 8;
    const float* in0 = R + kp * 68;
    const float* in1 = R + (kp + 16) * 68;
    unsigned long long acc0[4] = {0, 0, 0, 0}, acc1[4] = {0, 0, 0, 0};
#pragma unroll 4
    for (int ci = 0; ci < 64; ci++) {
        unsigned long long a0 = pack2(in0[ci]);
        unsigned long long a1 = pack2(in1[ci]);
        const ulonglong2* wr = (const ulonglong2*)(Wf + ci * 64 + co0);
        ulonglong2 w0 = wr[0], w1 = wr[1];
        fma2(acc0[0], a0, w0.x); fma2(acc1[0], a1, w0.x);
        fma2(acc0[1], a0, w0.y); fma2(acc1[1], a1, w0.y);
        fma2(acc0[2], a0, w1.x); fma2(acc1[2], a1, w1.x);
        fma2(acc0[3], a0, w1.y); fma2(acc1[3], a1, w1.y);
    }
    float2* o0 = (float2*)(out + (size_t)(base + kp) * 64 + co0);
    float2* o1 = (float2*)(out + (size_t)(base + kp + 16) * 64 + co0);
#pragma unroll
    for (int p = 0; p < 4; p++) { o0[p] = unpack2(acc0[p]); o1[p] = unpack2(acc1[p]); }
}

// ============================================================================
// 3b) GEMM1: fused gather + layer0 + layer1.  Block = 128 rows (4 segments),
//     256 threads, thread tile 4 rows x 8 cols (f32x2).  Writes X2.
// ============================================================================
#define AST 69   // padded A-tile stride

__global__ void __launch_bounds__(256) gemm1_kernel(
    const float* __restrict__ xyz, const float* __restrict__ newxyz,
    const float* __restrict__ fW0,
    const float* __restrict__ W0, const float* __restrict__ b0,
    const float* __restrict__ g0, const float* __restrict__ be0,
    const float* __restrict__ m0, const float* __restrict__ v0,
    const float* __restrict__ W1, const float* __restrict__ b1,
    const float* __restrict__ g1, const float* __restrict__ be1,
    const float* __restrict__ m1, const float* __restrict__ v1,
    float* __restrict__ X2)
{
    __shared__ float As[128 * AST];     // 8832
    __shared__ float Ws[64 * 64];       // 4096
    __shared__ float W0s[192];
    __shared__ float bn0[192];
    __shared__ float bn1[192];
    __shared__ float gxs[128 * 4];
    __shared__ int   sidx[128];
    __shared__ float qv[12];

    const int t = threadIdx.x;
    const int seg0 = blockIdx.x * 4;          // 4 segments per block
    const size_t row0 = (size_t)seg0 * 32;

    // stage weights/constants
    for (int i = t; i < 4096; i += 256) Ws[i] = W1[i];
    if (t < 192) W0s[t] = W0[t];
    if (t < 64) {
        float s0 = g0[t] * rsqrtf(v0[t] + 1e-3f);
        bn0[t] = s0; bn0[64 + t] = be0[t] - m0[t] * s0; bn0[128 + t] = b0[t];
        float s1 = g1[t] * rsqrtf(v1[t] + 1e-3f);
        bn1[t] = s1; bn1[64 + t] = be1[t] - m1[t] * s1; bn1[128 + t] = b1[t];
    }
    if (t < 128) sidx[t] = g_knn[row0 + t];
    if (t < 12)  qv[t] = newxyz[seg0 * 3 + t];
    __syncthreads();

    // gather: 2 threads per row (row = t>>1, half l = t&1)
    {
        const int r = t >> 1, l = t & 1;
        const int js = r >> 5;
        const int b  = (seg0 + js) >> 10;
        const int id = sidx[r];
        const float* fr = fW0 + ((size_t)b * N_ + id) * 64 + l * 32;
        float* dst = As + r * AST + l * 32;
#pragma unroll
        for (int j = 0; j < 8; j++) {
            float4 v = *(const float4*)(fr + j * 4);
            dst[4 * j + 0] = v.x; dst[4 * j + 1] = v.y;
            dst[4 * j + 2] = v.z; dst[4 * j + 3] = v.w;
        }
        if (l == 0) {
            const float* xr = xyz + ((size_t)b * N_ + id) * 3;
            gxs[r * 4 + 0] = __fsub_rn(xr[0], qv[js * 3 + 0]);
            gxs[r * 4 + 1] = __fsub_rn(xr[1], qv[js * 3 + 1]);
            gxs[r * 4 + 2] = __fsub_rn(xr[2], qv[js * 3 + 2]);
        }
    }
    __syncthreads();

    // layer-0 transform in smem: As <- bn0(relu(As + gx@W0a + b0))
    for (int i = t; i < 128 * 64; i += 256) {
        const int r = i >> 6, c = i & 63;
        float v = As[r * AST + c];
        v += gxs[r * 4 + 0] * W0s[c];
        v += gxs[r * 4 + 1] * W0s[64 + c];
        v += gxs[r * 4 + 2] * W0s[128 + c];
        v = fmaxf(v + bn0[128 + c], 0.0f);
        As[r * AST + c] = v * bn0[c] + bn0[64 + c];
    }
    __syncthreads();

    // GEMM: 4 rows x 8 cols per thread
    const int rg = t >> 3, cg = t & 7;
    const int r0 = rg * 4, co0 = cg * 8;

    unsigned long long acc[4][4];
#pragma unroll
    for (int i = 0; i < 4; i++)
#pragma unroll
        for (int p = 0; p < 4; p++) acc[i][p] = 0;

#pragma unroll 4
    for (int ci = 0; ci < 64; ci++) {
        const ulonglong2* wr = (const ulonglong2*)(Ws + ci * 64 + co0);
        ulonglong2 w0 = wr[0], w1 = wr[1];
#pragma unroll
        for (int i = 0; i < 4; i++) {
            unsigned long long a = pack2(As[(r0 + i) * AST + ci]);
            fma2(acc[i][0], a, w0.x);
            fma2(acc[i][1], a, w0.y);
            fma2(acc[i][2], a, w1.x);
            fma2(acc[i][3], a, w1.y);
        }
    }

    // epilogue: bn1 + write X2
#pragma unroll
    for (int i = 0; i < 4; i++) {
        float o[8];
#pragma unroll
        for (int p = 0; p < 4; p++) {
            float2 v = unpack2(acc[i][p]);
            int ca = co0 + 2 * p, cb = ca + 1;
            o[2 * p]     = fmaxf(v.x + bn1[128 + ca], 0.0f) * bn1[ca] + bn1[64 + ca];
            o[2 * p + 1] = fmaxf(v.y + bn1[128 + cb], 0.0f) * bn1[cb] + bn1[64 + cb];
        }
        float4* dst = (float4*)(X2 + (row0 + r0 + i) * 64 + co0);
        dst[0] = make_float4(o[0], o[1], o[2], o[3]);
        dst[1] = make_float4(o[4], o[5], o[6], o[7]);
    }
}

// ============================================================================
// 3c) GEMM2: layer2 + maxpool.  Block = 64 rows (2 segments) x 128 cols,
//     256 threads, thread tile 4 rows x 8 cols.
// ============================================================================
__global__ void __launch_bounds__(256) gemm2_kernel(
    const float* __restrict__ X2,
    const float* __restrict__ W2, const float* __restrict__ b2,
    const float* __restrict__ g2, const float* __restrict__ be2,
    const float* __restrict__ m2, const float* __restrict__ v2,
    float* __restrict__ outp)
{
    __shared__ float As[64 * AST];      // 4416
    __shared__ float Ws[64 * 128];      // 8192
    __shared__ float bn2[384];
    __shared__ float pool[16 * 130];    // 2080

    const int t = threadIdx.x;
    const int seg0 = blockIdx.x * 2;
    const size_t row0 = (size_t)seg0 * 32;

    for (int i = t; i < 8192; i += 256) Ws[i] = W2[i];
    if (t < 128) {
        float s2 = g2[t] * rsqrtf(v2[t] + 1e-3f);
        bn2[t] = s2; bn2[128 + t] = be2[t] - m2[t] * s2; bn2[256 + t] = b2[t];
    }
    // load A tile (64 x 64)
    for (int i = t; i < 64 * 16; i += 256) {
        const int r = i >> 4, q = i & 15;
        float4 v = *(const float4*)(X2 + (row0 + r) * 64 + q * 4);
        float* d = As + r * AST + q * 4;
        d[0] = v.x; d[1] = v.y; d[2] = v.z; d[3] = v.w;
    }
    __syncthreads();

    const int rg = t >> 4, cg = t & 15;     // 16 x 16
    const int r0 = rg * 4, co0 = cg * 8;

    unsigned long long acc[4][4];
#pragma unroll
    for (int i = 0; i < 4; i++)
#pragma unroll
        for (int p = 0; p < 4; p++) acc[i][p] = 0;

#pragma unroll 4
    for (int ci = 0; ci < 64; ci++) {
        const ulonglong2* wr = (const ulonglong2*)(Ws + ci * 128 + co0);
        ulonglong2 w0 = wr[0], w1 = wr[1];
#pragma unroll
        for (int i = 0; i < 4; i++) {
            unsigned long long a = pack2(As[(r0 + i) * AST + ci]);
            fma2(acc[i][0], a, w0.x);
            fma2(acc[i][1], a, w0.y);
            fma2(acc[i][2], a, w1.x);
            fma2(acc[i][3], a, w1.y);
        }
    }

    // bn2 + per-thread max over 4 rows (all within one segment: rg<8 -> seg0, else seg1)
    float pm[8];
#pragma unroll
    for (int j = 0; j < 8; j++) pm[j] = -CUDART_INF_F;
#pragma unroll
    for (int i = 0; i < 4; i++) {
#pragma unroll
        for (int p = 0; p < 4; p++) {
            float2 v = unpack2(acc[i][p]);
            int ca = co0 + 2 * p, cb = ca + 1;
            float oa = fmaxf(v.x + bn2[256 + ca], 0.0f) * bn2[ca] + bn2[128 + ca];
            float ob = fmaxf(v.y + bn2[256 + cb], 0.0f) * bn2[cb] + bn2[128 + cb];
            pm[2 * p]     = fmaxf(pm[2 * p], oa);
            pm[2 * p + 1] = fmaxf(pm[2 * p + 1], ob);
        }
    }
#pragma unroll
    for (int j = 0; j < 8; j++) pool[rg * 130 + co0 + j] = pm[j];
    __syncthreads();

    // final reduce: 2 segments x 128 cols = 256 outputs, one per thread
    {
        const int seg = t >> 7, c = t & 127;
        float m = -CUDART_INF_F;
#pragma unroll
        for (int u = 0; u < 8; u++) m = fmaxf(m, pool[(seg * 8 + u) * 130 + c]);
        outp[(size_t)(seg0 + seg) * 128 + c] = m;
    }
}

// ============================================================================
extern "C" void kernel_launch(void* const* d_in, const int* in_sizes, int n_in,
                              void* d_out, int out_size)
{
    (void)in_sizes; (void)n_in; (void)out_size;
    const float* xyz  = (const float*)d_in[0];
    const float* feat = (const float*)d_in[1];
    const float* P[18];
    for (int i = 0; i < 18; i++) P[i] = (const float*)d_in[2 + i];

    float* out    = (float*)d_out;
    float* newxyz = out;
    float* pooled = out + (size_t)B_ * S_ * 3;

    float* fW0;  cudaGetSymbolAddress((void**)&fW0, g_fW0);
    float* X2;   cudaGetSymbolAddress((void**)&X2,  g_X2);

    const int fps_smem = 3 * N_ * 4;
    const int knn_smem = (3 * N_ + N_ + 256) * 4 + NCAND * 8;

    cudaFuncSetAttribute(fps_kernel, cudaFuncAttributeMaxDynamicSharedMemorySize, fps_smem);
    cudaFuncSetAttribute(knn_kernel, cudaFuncAttributeMaxDynamicSharedMemorySize, knn_smem);

    pre_kernel<<<B_ * N_ / 32, 128>>>(feat, P[0], fW0);
    fps_kernel<<<B_, 1024, fps_smem>>>(xyz, newxyz);
    knn_kernel<<<B_ * S_ / 16, 256, knn_smem>>>(xyz, newxyz);
    gemm1_kernel<<<B_ * S_ / 4, 256>>>(
        xyz, newxyz, fW0,
        P[0], P[1], P[2], P[3], P[4], P[5],
        P[6], P[7], P[8], P[9], P[10], P[11],
        X2);
    gemm2_kernel<<<B_ * S_ / 2, 256>>>(
        X2, P[12], P[13], P[14], P[15], P[16], P[17], pooled);
}

// round 6
// speedup vs baseline: 2.8200x; 1.1808x over previous
#include <cuda_runtime.h>
#include <math_constants.h>
#include <cstddef>

#define B_   16
#define N_   4096
#define S_   1024
#define K_   32
#define CF_  64

// device scratch (no allocation allowed; zero-initialized at module load)
__device__ int   g_knn[B_ * S_ * K_];
__device__ float g_fW0[B_ * N_ * 64];     // feat @ W0[3:67]  (16 MB)
__device__ float g_nxyz[B_ * S_ * 3];     // centroid scratch (never poisoned)
__device__ int   g_flag[B_ * S_ / 16];    // monotonic progress flags

// ---------------------------------------------------------------- helpers
__device__ __forceinline__ unsigned long long pack2(float a) {
    unsigned long long r;
    asm("mov.b64 %0, {%1, %1};" : "=l"(r) : "f"(a));
    return r;
}
__device__ __forceinline__ void fma2(unsigned long long& d,
                                     unsigned long long a, unsigned long long b) {
    asm("fma.rn.f32x2 %0, %1, %2, %0;" : "+l"(d) : "l"(a), "l"(b));
}
__device__ __forceinline__ float2 unpack2(unsigned long long v) {
    float2 f;
    asm("mov.b64 {%0, %1}, %2;" : "=f"(f.x), "=f"(f.y) : "l"(v));
    return f;
}
__device__ __forceinline__ int ld_acq(const int* p) {
    int v;
    asm volatile("ld.acquire.gpu.global.b32 %0, [%1];" : "=r"(v) : "l"(p) : "memory");
    return v;
}
__device__ __forceinline__ void st_rel(int* p, int v) {
    asm volatile("st.release.gpu.global.b32 [%0], %1;" :: "l"(p), "r"(v) : "memory");
}

// ============================================================================
// FPS body — block b, 1024 threads. Bit-correct vs reference.
// ============================================================================
__device__ void fps_body(int b, float* sm, const float* __restrict__ xyz,
                         float* __restrict__ newxyz)
{
    float* sx = sm;
    float* sy = sm + N_;
    float* sz = sm + 2 * N_;
    __shared__ unsigned pv[2][32];
    __shared__ int      pi[2][32];

    const int t = threadIdx.x;
    const int lane = t & 31, warp = t >> 5;
    const float* base = xyz + (size_t)b * N_ * 3;

    float px[4], py[4], pz[4], dd[4];
#pragma unroll
    for (int j = 0; j < 4; j++) {
        int p = t + j * 1024;
        float x = base[3 * p + 0], y = base[3 * p + 1], z = base[3 * p + 2];
        px[j] = x; py[j] = y; pz[j] = z;
        sx[p] = x; sy[p] = y; sz[p] = z;
        dd[j] = 1e10f;
    }
    __syncthreads();

    int far = 0;
    for (int it = 0; it < S_; it++) {
        const int pr = it & 1;
        const float cx = sx[far], cy = sy[far], cz = sz[far];

        unsigned bvu = 0u;
        int      bi  = 0x7fffffff;
#pragma unroll
        for (int j = 0; j < 4; j++) {
            float dx = __fsub_rn(px[j], cx);
            float dy = __fsub_rn(py[j], cy);
            float dz = __fsub_rn(pz[j], cz);
            float d2 = __fadd_rn(__fadd_rn(__fmul_rn(dx, dx), __fmul_rn(dy, dy)),
                                 __fmul_rn(dz, dz));
            float nd = fminf(dd[j], d2);
            dd[j] = nd;
            unsigned u = __float_as_uint(nd);
            int idx = t + j * 1024;
            if (u > bvu || (u == bvu && idx < bi)) { bvu = u; bi = idx; }
        }
        unsigned rv = __reduce_max_sync(0xffffffffu, bvu);
        int      ri = __reduce_min_sync(0xffffffffu, (bvu == rv) ? bi : 0x7fffffff);
        if (lane == 0) { pv[pr][warp] = rv; pi[pr][warp] = ri; }
        __syncthreads();

        unsigned v  = pv[pr][lane];
        int      ii = pi[pr][lane];
        unsigned mv = __reduce_max_sync(0xffffffffu, v);
        far         = __reduce_min_sync(0xffffffffu, (v == mv) ? ii : 0x7fffffff);

        if (t == 0) {
            const size_t o = (size_t)(b * S_ + it) * 3;
            float x = sx[far], y = sy[far], z = sz[far];
            newxyz[o + 0] = x; newxyz[o + 1] = y; newxyz[o + 2] = z;
            g_nxyz[o + 0] = x; g_nxyz[o + 1] = y; g_nxyz[o + 2] = z;
            if ((it & 15) == 15)
                st_rel(&g_flag[(b * S_ + it) >> 4], 1);
        }
    }
}

// ============================================================================
// PRE body — 1024 threads, 256 points: g_fW0 = feat @ W0[3:67]
// smem: Wf 4096 fl | R 256*68 fl
// ============================================================================
__device__ void pre_body(int pb, float* sm, const float* __restrict__ feat,
                         const float* __restrict__ W0)
{
    float* Wf = sm;
    float* R  = sm + 4096;
    const int t = threadIdx.x;
    const int base = pb * 256;

    for (int i = t; i < 4096; i += 1024) Wf[i] = W0[192 + i];
    {
        const int k = t >> 2, l = t & 3;
        const float* fr = feat + (size_t)(base + k) * 64;
        float* dst = R + k * 68;
#pragma unroll
        for (int j = 0; j < 4; j++) {
            float4 v = *(const float4*)(fr + (l + 4 * j) * 4);
            float* d = dst + (l + 4 * j) * 4;
            d[0] = v.x; d[1] = v.y; d[2] = v.z; d[3] = v.w;
        }
    }
    __syncthreads();

    const int rg = t >> 3, cg = t & 7;
    const int r0 = rg * 2, co0 = cg * 8;
    const float* in0 = R + r0 * 68;
    const float* in1 = R + (r0 + 1) * 68;
    unsigned long long acc0[4] = {0, 0, 0, 0}, acc1[4] = {0, 0, 0, 0};
#pragma unroll 4
    for (int ci = 0; ci < 64; ci++) {
        unsigned long long a0 = pack2(in0[ci]);
        unsigned long long a1 = pack2(in1[ci]);
        const ulonglong2* wr = (const ulonglong2*)(Wf + ci * 64 + co0);
        ulonglong2 w0 = wr[0], w1 = wr[1];
        fma2(acc0[0], a0, w0.x); fma2(acc1[0], a1, w0.x);
        fma2(acc0[1], a0, w0.y); fma2(acc1[1], a1, w0.y);
        fma2(acc0[2], a0, w1.x); fma2(acc1[2], a1, w1.x);
        fma2(acc0[3], a0, w1.y); fma2(acc1[3], a1, w1.y);
    }
    float2* o0 = (float2*)(g_fW0 + (size_t)(base + r0) * 64 + co0);
    float2* o1 = (float2*)(g_fW0 + (size_t)(base + r0 + 1) * 64 + co0);
#pragma unroll
    for (int p = 0; p < 4; p++) { o0[p] = unpack2(acc0[p]); o1[p] = unpack2(acc1[p]); }
}

// ============================================================================
// KNN body — 1024 threads, 16 queries; spins on fps progress flag.
// ============================================================================
__device__ __forceinline__ void scan_select(const unsigned* hist, unsigned NEED,
                                            unsigned* out_c, unsigned* out_r, int t)
{
    if (t < 32) {
        unsigned acc[8]; unsigned tl = 0;
#pragma unroll
        for (int j = 0; j < 8; j++) { acc[j] = hist[t * 8 + j]; tl += acc[j]; }
        unsigned run = tl;
#pragma unroll
        for (int off = 1; off < 32; off <<= 1) {
            unsigned n = __shfl_up_sync(0xffffffffu, run, off);
            if (t >= off) run += n;
        }
        unsigned excl = run - tl;
        if (excl < NEED && NEED <= run) {
            unsigned c = excl;
#pragma unroll
            for (int j = 0; j < 8; j++) {
                if (c + acc[j] >= NEED) { *out_c = t * 8 + j; *out_r = NEED - c; break; }
                c += acc[j];
            }
        }
    }
}

#define NCAND 256

__device__ void knn_body(int kb, float* sm, const float* __restrict__ xyz)
{
    float*    sx   = sm;
    float*    sy   = sm + N_;
    float*    sz   = sm + 2 * N_;
    unsigned* du   = (unsigned*)(sm + 3 * N_);
    unsigned* hist = du + N_;
    unsigned long long* cand = (unsigned long long*)(hist + 256);
    __shared__ unsigned s_c1, s_need1, s_c2, s_need2, s_cnt, s_ccnt;

    const int t = threadIdx.x;
    const int qbase = kb * 16;
    const int b = qbase >> 10;

    const float* bp = xyz + (size_t)b * N_ * 3;
    for (int i = t; i < N_ * 3; i += 1024) {
        float v = bp[i];
        int p = i / 3, c = i - 3 * p;
        (c == 0 ? sx : (c == 1 ? sy : sz))[p] = v;
    }

    // wait for fps to publish rows qbase..qbase+15
    if (t == 0) {
        while (ld_acq(&g_flag[qbase >> 4]) == 0) __nanosleep(200);
    }
    __syncthreads();

    for (int q = 0; q < 16; q++) {
        const int row = qbase + q;
        const float qx = g_nxyz[row * 3 + 0];
        const float qy = g_nxyz[row * 3 + 1];
        const float qz = g_nxyz[row * 3 + 2];
        const float a2 = __fadd_rn(__fadd_rn(__fmul_rn(qx, qx), __fmul_rn(qy, qy)),
                                   __fmul_rn(qz, qz));

        if (t < 256) hist[t] = 0;
        if (t == 0) { s_cnt = 0; s_ccnt = 0; }
        __syncthreads();

        for (int i = t; i < N_; i += 1024) {
            float x = sx[i], y = sy[i], z = sz[i];
            float b2 = __fadd_rn(__fadd_rn(__fmul_rn(x, x), __fmul_rn(y, y)),
                                 __fmul_rn(z, z));
            float ab = __fadd_rn(__fadd_rn(__fmul_rn(qx, x), __fmul_rn(qy, y)),
                                 __fmul_rn(qz, z));
            float d2 = fmaxf(__fadd_rn(__fsub_rn(a2, __fmul_rn(2.0f, ab)), b2), 0.0f);
            unsigned u = __float_as_uint(d2);
            du[i] = u;
            atomicAdd(&hist[u >> 24], 1u);
        }
        __syncthreads();

        scan_select(hist, K_, &s_c1, &s_need1, t);
        __syncthreads();
        const unsigned c1 = s_c1, need1 = s_need1;

        if (t < 256) hist[t] = 0;
        __syncthreads();
        for (int i = t; i < N_; i += 1024) {
            unsigned u = du[i];
            if ((u >> 24) == c1) atomicAdd(&hist[(u >> 16) & 255u], 1u);
        }
        __syncthreads();

        scan_select(hist, need1, &s_c2, &s_need2, t);
        __syncthreads();
        const unsigned thr16 = (c1 << 8) | s_c2;
        const unsigned need2 = s_need2;

        for (int i = t; i < N_; i += 1024) {
            unsigned u = du[i];
            unsigned k16 = u >> 16;
            if (k16 < thr16) {
                unsigned p = atomicAdd(&s_cnt, 1u);
                g_knn[(size_t)row * K_ + p] = i;
            } else if (k16 == thr16) {
                unsigned c = atomicAdd(&s_ccnt, 1u);
                if (c < NCAND) cand[c] = (((unsigned long long)u) << 12) | (unsigned)i;
            }
        }
        __syncthreads();

        if (t == 0) {
            int baseo = (int)s_cnt;
            int nc = (int)(s_ccnt < (unsigned)NCAND ? s_ccnt : (unsigned)NCAND);
            for (int j = 0; j < (int)need2; j++) {
                unsigned long long best = ~0ULL; int bj = 0;
                for (int m = 0; m < nc; m++)
                    if (cand[m] < best) { best = cand[m]; bj = m; }
                g_knn[(size_t)row * K_ + baseo + j] = (int)(best & 0xFFFu);
                cand[bj] = ~0ULL;
            }
        }
        __syncthreads();
    }
}

// ============================================================================
// FRONT kernel: blocks [0,16) fps | [16,272) pre | [272,1296) knn
// ============================================================================
#define FRONT_SMEM (21504 * 4)   // pre is largest: (4096 + 256*68) floats

__global__ void __launch_bounds__(1024) front_kernel(
    const float* __restrict__ xyz, const float* __restrict__ feat,
    const float* __restrict__ W0, float* __restrict__ newxyz)
{
    extern __shared__ float sm[];
    const int bid = blockIdx.x;
    if (bid < 16)            fps_body(bid, sm, xyz, newxyz);
    else if (bid < 16 + 256) pre_body(bid - 16, sm, feat, W0);
    else                     knn_body(bid - 272, sm, xyz);
}

// ============================================================================
// MLP kernel: fused gather + L0 + GEMM1 + GEMM2 + maxpool.
// Block = 64 rows (2 segments), 256 threads.
// ============================================================================
#define AST 69

// smem layout (floats):
//   As 0..4416 | X1s 4416..8832 | W1s 8832..12928 | W2s 12928..21120 |
//   W0s 21120..21312 | bn0 21312 | bn1 21504 | bn2 21696..22080 |
//   gxs 22080..22336 | pool 22336..24416
#define MLP_SMEM_FL 24416

__global__ void __launch_bounds__(256) mlp_kernel(
    const float* __restrict__ xyz, const float* __restrict__ fW0,
    const float* __restrict__ W0, const float* __restrict__ b0,
    const float* __restrict__ g0, const float* __restrict__ be0,
    const float* __restrict__ m0, const float* __restrict__ v0,
    const float* __restrict__ W1, const float* __restrict__ b1,
    const float* __restrict__ g1, const float* __restrict__ be1,
    const float* __restrict__ m1, const float* __restrict__ v1,
    const float* __restrict__ W2, const float* __restrict__ b2,
    const float* __restrict__ g2, const float* __restrict__ be2,
    const float* __restrict__ m2, const float* __restrict__ v2,
    float* __restrict__ outp)
{
    extern __shared__ float sm[];
    float* As   = sm;
    float* X1s  = sm + 4416;
    float* W1s  = sm + 8832;
    float* W2s  = sm + 12928;
    float* W0s  = sm + 21120;
    float* bn0  = sm + 21312;
    float* bn1  = sm + 21504;
    float* bn2  = sm + 21696;
    float* gxs  = sm + 22080;
    float* pool = sm + 22336;
    __shared__ int   sidx[64];
    __shared__ float qv[6];

    const int t = threadIdx.x;
    const int seg0 = blockIdx.x * 2;
    const size_t row0 = (size_t)seg0 * 32;

    // ---- stage weights / constants ----
    for (int i = t; i < 4096; i += 256) W1s[i] = W1[i];
    for (int i = t; i < 8192; i += 256) W2s[i] = W2[i];
    if (t < 192) W0s[t] = W0[t];
    if (t < 64) {
        float s0 = g0[t] * rsqrtf(v0[t] + 1e-3f);
        bn0[t] = s0; bn0[64 + t] = be0[t] - m0[t] * s0; bn0[128 + t] = b0[t];
        float s1 = g1[t] * rsqrtf(v1[t] + 1e-3f);
        bn1[t] = s1; bn1[64 + t] = be1[t] - m1[t] * s1; bn1[128 + t] = b1[t];
    }
    if (t < 128) {
        float s2 = g2[t] * rsqrtf(v2[t] + 1e-3f);
        bn2[t] = s2; bn2[128 + t] = be2[t] - m2[t] * s2; bn2[256 + t] = b2[t];
    }
    if (t < 64) sidx[t] = g_knn[row0 + t];
    if (t < 6)  qv[t] = g_nxyz[seg0 * 3 + t];
    __syncthreads();

    // ---- gather: 4 threads per row ----
    {
        const int r = t >> 2, l = t & 3;
        const int js = r >> 5;
        const int b  = (seg0 + js) >> 10;
        const int id = sidx[r];
        const float* fr = fW0 + ((size_t)b * N_ + id) * 64 + l * 16;
        float* dst = As + r * AST + l * 16;
#pragma unroll
        for (int j = 0; j < 4; j++) {
            float4 v = *(const float4*)(fr + j * 4);
            dst[4 * j + 0] = v.x; dst[4 * j + 1] = v.y;
            dst[4 * j + 2] = v.z; dst[4 * j + 3] = v.w;
        }
        if (l == 0) {
            const float* xr = xyz + ((size_t)b * N_ + id) * 3;
            gxs[r * 4 + 0] = __fsub_rn(xr[0], qv[js * 3 + 0]);
            gxs[r * 4 + 1] = __fsub_rn(xr[1], qv[js * 3 + 1]);
            gxs[r * 4 + 2] = __fsub_rn(xr[2], qv[js * 3 + 2]);
        }
    }
    __syncthreads();

    // ---- layer-0 transform in smem ----
    for (int i = t; i < 64 * 64; i += 256) {
        const int r = i >> 6, c = i & 63;
        float v = As[r * AST + c];
        v += gxs[r * 4 + 0] * W0s[c];
        v += gxs[r * 4 + 1] * W0s[64 + c];
        v += gxs[r * 4 + 2] * W0s[128 + c];
        v = fmaxf(v + bn0[128 + c], 0.0f);
        As[r * AST + c] = v * bn0[c] + bn0[64 + c];
    }
    __syncthreads();

    // ---- GEMM1: 64x64, thread tile 2 rows x 8 cols ----
    {
        const int rg = t >> 3, cg = t & 7;
        const int r0 = rg * 2, co0 = cg * 8;

        unsigned long long acc0[4] = {0, 0, 0, 0}, acc1[4] = {0, 0, 0, 0};
#pragma unroll 4
        for (int ci = 0; ci < 64; ci++) {
            unsigned long long a0 = pack2(As[r0 * AST + ci]);
            unsigned long long a1 = pack2(As[(r0 + 1) * AST + ci]);
            const ulonglong2* wr = (const ulonglong2*)(W1s + ci * 64 + co0);
            ulonglong2 w0 = wr[0], w1 = wr[1];
            fma2(acc0[0], a0, w0.x); fma2(acc1[0], a1, w0.x);
            fma2(acc0[1], a0, w0.y); fma2(acc1[1], a1, w0.y);
            fma2(acc0[2], a0, w1.x); fma2(acc1[2], a1, w1.x);
            fma2(acc0[3], a0, w1.y); fma2(acc1[3], a1, w1.y);
        }
        float* o0 = X1s + r0 * AST + co0;
        float* o1 = X1s + (r0 + 1) * AST + co0;
#pragma unroll
        for (int p = 0; p < 4; p++) {
            float2 v0 = unpack2(acc0[p]), v1 = unpack2(acc1[p]);
            int ca = co0 + 2 * p, cb = ca + 1;
            o0[2 * p]     = fmaxf(v0.x + bn1[128 + ca], 0.0f) * bn1[ca] + bn1[64 + ca];
            o0[2 * p + 1] = fmaxf(v0.y + bn1[128 + cb], 0.0f) * bn1[cb] + bn1[64 + cb];
            o1[2 * p]     = fmaxf(v1.x + bn1[128 + ca], 0.0f) * bn1[ca] + bn1[64 + ca];
            o1[2 * p + 1] = fmaxf(v1.y + bn1[128 + cb], 0.0f) * bn1[cb] + bn1[64 + cb];
        }
    }
    __syncthreads();

    // ---- GEMM2: 64x128, thread tile 4 rows x 8 cols + pool ----
    {
        const int rg = t >> 4, cg = t & 15;
        const int r0 = rg * 4, co0 = cg * 8;

        unsigned long long acc[4][4];
#pragma unroll
        for (int i = 0; i < 4; i++)
#pragma unroll
            for (int p = 0; p < 4; p++) acc[i][p] = 0;

#pragma unroll 4
        for (int ci = 0; ci < 64; ci++) {
            const ulonglong2* wr = (const ulonglong2*)(W2s + ci * 128 + co0);
            ulonglong2 w0 = wr[0], w1 = wr[1];
#pragma unroll
            for (int i = 0; i < 4; i++) {
                unsigned long long a = pack2(X1s[(r0 + i) * AST + ci]);
                fma2(acc[i][0], a, w0.x);
                fma2(acc[i][1], a, w0.y);
                fma2(acc[i][2], a, w1.x);
                fma2(acc[i][3], a, w1.y);
            }
        }

        float pm[8];
#pragma unroll
        for (int j = 0; j < 8; j++) pm[j] = -CUDART_INF_F;
#pragma unroll
        for (int i = 0; i < 4; i++) {
#pragma unroll
            for (int p = 0; p < 4; p++) {
                float2 v = unpack2(acc[i][p]);
                int ca = co0 + 2 * p, cb = ca + 1;
                float oa = fmaxf(v.x + bn2[256 + ca], 0.0f) * bn2[ca] + bn2[128 + ca];
                float ob = fmaxf(v.y + bn2[256 + cb], 0.0f) * bn2[cb] + bn2[128 + cb];
                pm[2 * p]     = fmaxf(pm[2 * p], oa);
                pm[2 * p + 1] = fmaxf(pm[2 * p + 1], ob);
            }
        }
#pragma unroll
        for (int j = 0; j < 8; j++) pool[rg * 130 + co0 + j] = pm[j];
    }
    __syncthreads();

    // ---- final reduce: 2 segments x 128 cols ----
    {
        const int seg = t >> 7, c = t & 127;
        float m = -CUDART_INF_F;
#pragma unroll
        for (int u = 0; u < 8; u++) m = fmaxf(m, pool[(seg * 8 + u) * 130 + c]);
        outp[(size_t)(seg0 + seg) * 128 + c] = m;
    }
}

// ============================================================================
extern "C" void kernel_launch(void* const* d_in, const int* in_sizes, int n_in,
                              void* d_out, int out_size)
{
    (void)in_sizes; (void)n_in; (void)out_size;
    const float* xyz  = (const float*)d_in[0];
    const float* feat = (const float*)d_in[1];
    const float* P[18];
    for (int i = 0; i < 18; i++) P[i] = (const float*)d_in[2 + i];

    float* out    = (float*)d_out;
    float* newxyz = out;
    float* pooled = out + (size_t)B_ * S_ * 3;

    float* fW0;  cudaGetSymbolAddress((void**)&fW0, g_fW0);

    cudaFuncSetAttribute(front_kernel, cudaFuncAttributeMaxDynamicSharedMemorySize, FRONT_SMEM);
    cudaFuncSetAttribute(mlp_kernel,   cudaFuncAttributeMaxDynamicSharedMemorySize, MLP_SMEM_FL * 4);

    front_kernel<<<16 + 256 + 1024, 1024, FRONT_SMEM>>>(xyz, feat, P[0], newxyz);
    mlp_kernel<<<B_ * S_ / 2, 256, MLP_SMEM_FL * 4>>>(
        xyz, fW0,
        P[0],  P[1],  P[2],  P[3],  P[4],  P[5],
        P[6],  P[7],  P[8],  P[9],  P[10], P[11],
        P[12], P[13], P[14], P[15], P[16], P[17],
        pooled);
}

// round 7
// speedup vs baseline: 3.4564x; 1.2257x over previous
#include <cuda_runtime.h>
#include <math_constants.h>
#include <cstddef>

#define B_   16
#define N_   4096
#define S_   1024
#define K_   32
#define CF_  64

// device scratch (no allocation allowed; zero-initialized at module load)
__device__ int   g_knn[B_ * S_ * K_];
__device__ float g_fW0[B_ * N_ * 64];     // feat @ W0[3:67]  (16 MB)
__device__ float g_nxyz[B_ * S_ * 3];     // centroid scratch (never poisoned)
__device__ int   g_flag[B_ * S_ / 16];    // monotonic progress flags

// ---------------------------------------------------------------- helpers
__device__ __forceinline__ unsigned long long pack2(float a) {
    unsigned long long r;
    asm("mov.b64 %0, {%1, %1};" : "=l"(r) : "f"(a));
    return r;
}
__device__ __forceinline__ void fma2(unsigned long long& d,
                                     unsigned long long a, unsigned long long b) {
    asm("fma.rn.f32x2 %0, %1, %2, %0;" : "+l"(d) : "l"(a), "l"(b));
}
__device__ __forceinline__ float2 unpack2(unsigned long long v) {
    float2 f;
    asm("mov.b64 {%0, %1}, %2;" : "=f"(f.x), "=f"(f.y) : "l"(v));
    return f;
}
__device__ __forceinline__ int ld_acq(const int* p) {
    int v;
    asm volatile("ld.acquire.gpu.global.b32 %0, [%1];" : "=r"(v) : "l"(p) : "memory");
    return v;
}
__device__ __forceinline__ void st_rel(int* p, int v) {
    asm volatile("st.release.gpu.global.b32 [%0], %1;" :: "l"(p), "r"(v) : "memory");
}

// ============================================================================
// FPS body — block b, 1024 threads. Bit-correct vs reference.
// ============================================================================
__device__ void fps_body(int b, float* sm, const float* __restrict__ xyz,
                         float* __restrict__ newxyz)
{
    float* sx = sm;
    float* sy = sm + N_;
    float* sz = sm + 2 * N_;
    __shared__ unsigned pv[2][32];
    __shared__ int      pi[2][32];

    const int t = threadIdx.x;
    const int lane = t & 31, warp = t >> 5;
    const float* base = xyz + (size_t)b * N_ * 3;

    float px[4], py[4], pz[4], dd[4];
#pragma unroll
    for (int j = 0; j < 4; j++) {
        int p = t + j * 1024;
        float x = base[3 * p + 0], y = base[3 * p + 1], z = base[3 * p + 2];
        px[j] = x; py[j] = y; pz[j] = z;
        sx[p] = x; sy[p] = y; sz[p] = z;
        dd[j] = 1e10f;
    }
    __syncthreads();

    int far = 0;
    for (int it = 0; it < S_; it++) {
        const int pr = it & 1;
        const float cx = sx[far], cy = sy[far], cz = sz[far];

        unsigned bvu = 0u;
        int      bi  = 0x7fffffff;
#pragma unroll
        for (int j = 0; j < 4; j++) {
            float dx = __fsub_rn(px[j], cx);
            float dy = __fsub_rn(py[j], cy);
            float dz = __fsub_rn(pz[j], cz);
            float d2 = __fadd_rn(__fadd_rn(__fmul_rn(dx, dx), __fmul_rn(dy, dy)),
                                 __fmul_rn(dz, dz));
            float nd = fminf(dd[j], d2);
            dd[j] = nd;
            unsigned u = __float_as_uint(nd);
            int idx = t + j * 1024;
            if (u > bvu || (u == bvu && idx < bi)) { bvu = u; bi = idx; }
        }
        unsigned rv = __reduce_max_sync(0xffffffffu, bvu);
        int      ri = __reduce_min_sync(0xffffffffu, (bvu == rv) ? bi : 0x7fffffff);
        if (lane == 0) { pv[pr][warp] = rv; pi[pr][warp] = ri; }
        __syncthreads();

        unsigned v  = pv[pr][lane];
        int      ii = pi[pr][lane];
        unsigned mv = __reduce_max_sync(0xffffffffu, v);
        far         = __reduce_min_sync(0xffffffffu, (v == mv) ? ii : 0x7fffffff);

        if (t == 0) {
            const size_t o = (size_t)(b * S_ + it) * 3;
            float x = sx[far], y = sy[far], z = sz[far];
            newxyz[o + 0] = x; newxyz[o + 1] = y; newxyz[o + 2] = z;
            g_nxyz[o + 0] = x; g_nxyz[o + 1] = y; g_nxyz[o + 2] = z;
            if ((it & 15) == 15)
                st_rel(&g_flag[(b * S_ + it) >> 4], 1);
        }
    }
}

// ============================================================================
// PRE body — 1024 threads, 256 points: g_fW0 = feat @ W0[3:67]
// ============================================================================
__device__ void pre_body(int pb, float* sm, const float* __restrict__ feat,
                         const float* __restrict__ W0)
{
    float* Wf = sm;
    float* R  = sm + 4096;
    const int t = threadIdx.x;
    const int base = pb * 256;

    for (int i = t; i < 4096; i += 1024) Wf[i] = W0[192 + i];
    {
        const int k = t >> 2, l = t & 3;
        const float* fr = feat + (size_t)(base + k) * 64;
        float* dst = R + k * 68;
#pragma unroll
        for (int j = 0; j < 4; j++) {
            float4 v = *(const float4*)(fr + (l + 4 * j) * 4);
            float* d = dst + (l + 4 * j) * 4;
            d[0] = v.x; d[1] = v.y; d[2] = v.z; d[3] = v.w;
        }
    }
    __syncthreads();

    const int rg = t >> 3, cg = t & 7;
    const int r0 = rg * 2, co0 = cg * 8;
    const float* in0 = R + r0 * 68;
    const float* in1 = R + (r0 + 1) * 68;
    unsigned long long acc0[4] = {0, 0, 0, 0}, acc1[4] = {0, 0, 0, 0};
#pragma unroll 4
    for (int ci = 0; ci < 64; ci++) {
        unsigned long long a0 = pack2(in0[ci]);
        unsigned long long a1 = pack2(in1[ci]);
        const ulonglong2* wr = (const ulonglong2*)(Wf + ci * 64 + co0);
        ulonglong2 w0 = wr[0], w1 = wr[1];
        fma2(acc0[0], a0, w0.x); fma2(acc1[0], a1, w0.x);
        fma2(acc0[1], a0, w0.y); fma2(acc1[1], a1, w0.y);
        fma2(acc0[2], a0, w1.x); fma2(acc1[2], a1, w1.x);
        fma2(acc0[3], a0, w1.y); fma2(acc1[3], a1, w1.y);
    }
    float2* o0 = (float2*)(g_fW0 + (size_t)(base + r0) * 64 + co0);
    float2* o1 = (float2*)(g_fW0 + (size_t)(base + r0 + 1) * 64 + co0);
#pragma unroll
    for (int p = 0; p < 4; p++) { o0[p] = unpack2(acc0[p]); o1[p] = unpack2(acc1[p]); }
}

// ============================================================================
// KNN body — 1024 threads, 16 queries; spins on fps progress flag.
// ============================================================================
__device__ __forceinline__ void scan_select(const unsigned* hist, unsigned NEED,
                                            unsigned* out_c, unsigned* out_r, int t)
{
    if (t < 32) {
        unsigned acc[8]; unsigned tl = 0;
#pragma unroll
        for (int j = 0; j < 8; j++) { acc[j] = hist[t * 8 + j]; tl += acc[j]; }
        unsigned run = tl;
#pragma unroll
        for (int off = 1; off < 32; off <<= 1) {
            unsigned n = __shfl_up_sync(0xffffffffu, run, off);
            if (t >= off) run += n;
        }
        unsigned excl = run - tl;
        if (excl < NEED && NEED <= run) {
            unsigned c = excl;
#pragma unroll
            for (int j = 0; j < 8; j++) {
                if (c + acc[j] >= NEED) { *out_c = t * 8 + j; *out_r = NEED - c; break; }
                c += acc[j];
            }
        }
    }
}

#define NCAND 256

__device__ void knn_body(int kb, float* sm, const float* __restrict__ xyz)
{
    float*    sx   = sm;
    float*    sy   = sm + N_;
    float*    sz   = sm + 2 * N_;
    unsigned* du   = (unsigned*)(sm + 3 * N_);
    unsigned* hist = du + N_;
    unsigned long long* cand = (unsigned long long*)(hist + 256);
    __shared__ unsigned s_c1, s_need1, s_c2, s_need2, s_cnt, s_ccnt;

    const int t = threadIdx.x;
    const int qbase = kb * 16;
    const int b = qbase >> 10;

    const float* bp = xyz + (size_t)b * N_ * 3;
    for (int i = t; i < N_ * 3; i += 1024) {
        float v = bp[i];
        int p = i / 3, c = i - 3 * p;
        (c == 0 ? sx : (c == 1 ? sy : sz))[p] = v;
    }

    if (t == 0) {
        while (ld_acq(&g_flag[qbase >> 4]) == 0) __nanosleep(200);
    }
    __syncthreads();

    for (int q = 0; q < 16; q++) {
        const int row = qbase + q;
        const float qx = g_nxyz[row * 3 + 0];
        const float qy = g_nxyz[row * 3 + 1];
        const float qz = g_nxyz[row * 3 + 2];
        const float a2 = __fadd_rn(__fadd_rn(__fmul_rn(qx, qx), __fmul_rn(qy, qy)),
                                   __fmul_rn(qz, qz));

        if (t < 256) hist[t] = 0;
        if (t == 0) { s_cnt = 0; s_ccnt = 0; }
        __syncthreads();

        for (int i = t; i < N_; i += 1024) {
            float x = sx[i], y = sy[i], z = sz[i];
            float b2 = __fadd_rn(__fadd_rn(__fmul_rn(x, x), __fmul_rn(y, y)),
                                 __fmul_rn(z, z));
            float ab = __fadd_rn(__fadd_rn(__fmul_rn(qx, x), __fmul_rn(qy, y)),
                                 __fmul_rn(qz, z));
            float d2 = fmaxf(__fadd_rn(__fsub_rn(a2, __fmul_rn(2.0f, ab)), b2), 0.0f);
            unsigned u = __float_as_uint(d2);
            du[i] = u;
            atomicAdd(&hist[u >> 24], 1u);
        }
        __syncthreads();

        scan_select(hist, K_, &s_c1, &s_need1, t);
        __syncthreads();
        const unsigned c1 = s_c1, need1 = s_need1;

        if (t < 256) hist[t] = 0;
        __syncthreads();
        for (int i = t; i < N_; i += 1024) {
            unsigned u = du[i];
            if ((u >> 24) == c1) atomicAdd(&hist[(u >> 16) & 255u], 1u);
        }
        __syncthreads();

        scan_select(hist, need1, &s_c2, &s_need2, t);
        __syncthreads();
        const unsigned thr16 = (c1 << 8) | s_c2;
        const unsigned need2 = s_need2;

        for (int i = t; i < N_; i += 1024) {
            unsigned u = du[i];
            unsigned k16 = u >> 16;
            if (k16 < thr16) {
                unsigned p = atomicAdd(&s_cnt, 1u);
                g_knn[(size_t)row * K_ + p] = i;
            } else if (k16 == thr16) {
                unsigned c = atomicAdd(&s_ccnt, 1u);
                if (c < NCAND) cand[c] = (((unsigned long long)u) << 12) | (unsigned)i;
            }
        }
        __syncthreads();

        if (t == 0) {
            int baseo = (int)s_cnt;
            int nc = (int)(s_ccnt < (unsigned)NCAND ? s_ccnt : (unsigned)NCAND);
            for (int j = 0; j < (int)need2; j++) {
                unsigned long long best = ~0ULL; int bj = 0;
                for (int m = 0; m < nc; m++)
                    if (cand[m] < best) { best = cand[m]; bj = m; }
                g_knn[(size_t)row * K_ + baseo + j] = (int)(best & 0xFFFu);
                cand[bj] = ~0ULL;
            }
        }
        __syncthreads();
    }
}

// ============================================================================
// FRONT kernel: blocks [0,16) fps | [16,272) pre | [272,1296) knn
// ============================================================================
#define FRONT_SMEM (21504 * 4)

__global__ void __launch_bounds__(1024) front_kernel(
    const float* __restrict__ xyz, const float* __restrict__ feat,
    const float* __restrict__ W0, float* __restrict__ newxyz)
{
    extern __shared__ float sm[];
    const int bid = blockIdx.x;
    if (bid < 16)            fps_body(bid, sm, xyz, newxyz);
    else if (bid < 16 + 256) pre_body(bid - 16, sm, feat, W0);
    else                     knn_body(bid - 272, sm, xyz);
}

// ============================================================================
// MLP: 256 rows (8 segments) per block, 256 threads, 8x8 register tiles.
// ============================================================================
#define RST 69

// smem (floats):
//  As   0..17664      (aliased by pool[32*132] after GEMM1)
//  X1s  17664..35328
//  W1s  35328..39424
//  W2s  39424..47616
//  W0s  47616..47808
//  bn0  47808..48000 | bn1 48000..48192 | bn2 48192..48576
//  gxs  48576..49600
#define MLP_SMEM_FL 49600

__global__ void __launch_bounds__(256) mlp_kernel(
    const float* __restrict__ xyz, const float* __restrict__ fW0,
    const float* __restrict__ W0, const float* __restrict__ b0,
    const float* __restrict__ g0, const float* __restrict__ be0,
    const float* __restrict__ m0, const float* __restrict__ v0,
    const float* __restrict__ W1, const float* __restrict__ b1,
    const float* __restrict__ g1, const float* __restrict__ be1,
    const float* __restrict__ m1, const float* __restrict__ v1,
    const float* __restrict__ W2, const float* __restrict__ b2,
    const float* __restrict__ g2, const float* __restrict__ be2,
    const float* __restrict__ m2, const float* __restrict__ v2,
    float* __restrict__ outp)
{
    extern __shared__ float sm[];
    float* As   = sm;
    float* X1s  = sm + 17664;
    float* W1s  = sm + 35328;
    float* W2s  = sm + 39424;
    float* W0s  = sm + 47616;
    float* bn0  = sm + 47808;
    float* bn1  = sm + 48000;
    float* bn2  = sm + 48192;
    float* gxs  = sm + 48576;
    float* pool = As;                    // alias: As dead after GEMM1
    __shared__ int   sidx[256];
    __shared__ float qv[24];

    const int t = threadIdx.x;
    const int seg0 = blockIdx.x * 8;
    const size_t row0 = (size_t)seg0 * 32;

    // ---- stage weights / constants ----
    for (int i = t; i < 4096; i += 256) W1s[i] = W1[i];
    for (int i = t; i < 8192; i += 256) W2s[i] = W2[i];
    if (t < 192) W0s[t] = W0[t];
    if (t < 64) {
        float s0 = g0[t] * rsqrtf(v0[t] + 1e-3f);
        bn0[t] = s0; bn0[64 + t] = be0[t] - m0[t] * s0; bn0[128 + t] = b0[t];
        float s1 = g1[t] * rsqrtf(v1[t] + 1e-3f);
        bn1[t] = s1; bn1[64 + t] = be1[t] - m1[t] * s1; bn1[128 + t] = b1[t];
    }
    if (t < 128) {
        float s2 = g2[t] * rsqrtf(v2[t] + 1e-3f);
        bn2[t] = s2; bn2[128 + t] = be2[t] - m2[t] * s2; bn2[256 + t] = b2[t];
    }
    sidx[t] = g_knn[row0 + t];
    if (t < 24) qv[t] = g_nxyz[seg0 * 3 + t];
    __syncthreads();

    // ---- gather: one thread per row ----
    {
        const int r = t;
        const int seg = r >> 5;
        const int b = (seg0 + seg) >> 10;
        const int id = sidx[r];
        const float4* fr = (const float4*)(fW0 + ((size_t)b * N_ + id) * 64);
        float* dst = As + r * RST;
#pragma unroll
        for (int j = 0; j < 16; j++) {
            float4 v = fr[j];
            dst[4 * j + 0] = v.x; dst[4 * j + 1] = v.y;
            dst[4 * j + 2] = v.z; dst[4 * j + 3] = v.w;
        }
        const float* xr = xyz + ((size_t)b * N_ + id) * 3;
        gxs[r * 4 + 0] = __fsub_rn(xr[0], qv[seg * 3 + 0]);
        gxs[r * 4 + 1] = __fsub_rn(xr[1], qv[seg * 3 + 1]);
        gxs[r * 4 + 2] = __fsub_rn(xr[2], qv[seg * 3 + 2]);
    }
    __syncthreads();

    // ---- layer-0 transform in smem ----
    for (int i = t; i < 256 * 64; i += 256) {
        const int r = i >> 6, c = i & 63;
        float v = As[r * RST + c];
        v += gxs[r * 4 + 0] * W0s[c];
        v += gxs[r * 4 + 1] * W0s[64 + c];
        v += gxs[r * 4 + 2] * W0s[128 + c];
        v = fmaxf(v + bn0[128 + c], 0.0f);
        As[r * RST + c] = v * bn0[c] + bn0[64 + c];
    }
    __syncthreads();

    const int rg = t >> 3, cg = t & 7;
    const int r0 = rg * 8;

    // ---- GEMM1: 256x64, 8 rows x 8 cols per thread ----
    {
        const int co = cg * 8;
        unsigned long long acc[8][4];
#pragma unroll
        for (int i = 0; i < 8; i++)
#pragma unroll
            for (int p = 0; p < 4; p++) acc[i][p] = 0;

#pragma unroll 2
        for (int ci = 0; ci < 64; ci++) {
            const ulonglong2* wr = (const ulonglong2*)(W1s + ci * 64 + co);
            ulonglong2 w0 = wr[0], w1 = wr[1];
#pragma unroll
            for (int i = 0; i < 8; i++) {
                unsigned long long a = pack2(As[(r0 + i) * RST + ci]);
                fma2(acc[i][0], a, w0.x);
                fma2(acc[i][1], a, w0.y);
                fma2(acc[i][2], a, w1.x);
                fma2(acc[i][3], a, w1.y);
            }
        }
#pragma unroll
        for (int i = 0; i < 8; i++) {
            float* o = X1s + (r0 + i) * RST + co;
#pragma unroll
            for (int p = 0; p < 4; p++) {
                float2 v = unpack2(acc[i][p]);
                int ca = co + 2 * p, cb = ca + 1;
                o[2 * p]     = fmaxf(v.x + bn1[128 + ca], 0.0f) * bn1[ca] + bn1[64 + ca];
                o[2 * p + 1] = fmaxf(v.y + bn1[128 + cb], 0.0f) * bn1[cb] + bn1[64 + cb];
            }
        }
    }
    __syncthreads();

    // ---- GEMM2: 256x128 in two 64-col passes, 8x8 per thread, fused pool ----
#pragma unroll 1
    for (int ph = 0; ph < 2; ph++) {
        const int co = ph * 64 + cg * 8;
        unsigned long long acc[8][4];
#pragma unroll
        for (int i = 0; i < 8; i++)
#pragma unroll
            for (int p = 0; p < 4; p++) acc[i][p] = 0;

#pragma unroll 2
        for (int ci = 0; ci < 64; ci++) {
            const ulonglong2* wr = (const ulonglong2*)(W2s + ci * 128 + co);
            ulonglong2 w0 = wr[0], w1 = wr[1];
#pragma unroll
            for (int i = 0; i < 8; i++) {
                unsigned long long a = pack2(X1s[(r0 + i) * RST + ci]);
                fma2(acc[i][0], a, w0.x);
                fma2(acc[i][1], a, w0.y);
                fma2(acc[i][2], a, w1.x);
                fma2(acc[i][3], a, w1.y);
            }
        }

        float pm[8];
#pragma unroll
        for (int j = 0; j < 8; j++) pm[j] = -CUDART_INF_F;
#pragma unroll
        for (int i = 0; i < 8; i++) {
#pragma unroll
            for (int p = 0; p < 4; p++) {
                float2 v = unpack2(acc[i][p]);
                int ca = co + 2 * p, cb = ca + 1;
                float oa = fmaxf(v.x + bn2[256 + ca], 0.0f) * bn2[ca] + bn2[128 + ca];
                float ob = fmaxf(v.y + bn2[256 + cb], 0.0f) * bn2[cb] + bn2[128 + cb];
                pm[2 * p]     = fmaxf(pm[2 * p], oa);
                pm[2 * p + 1] = fmaxf(pm[2 * p + 1], ob);
            }
        }
#pragma unroll
        for (int j = 0; j < 8; j++) pool[rg * 132 + co + j] = pm[j];
    }
    __syncthreads();

    // ---- final reduce: 8 segments x 128 cols (4 rgroups each) ----
#pragma unroll
    for (int u = 0; u < 4; u++) {
        const int idx = t + 256 * u;
        const int seg = idx >> 7, c = idx & 127;
        float m = -CUDART_INF_F;
#pragma unroll
        for (int v = 0; v < 4; v++)
            m = fmaxf(m, pool[(seg * 4 + v) * 132 + c]);
        outp[(size_t)(seg0 + seg) * 128 + c] = m;
    }
}

// ============================================================================
extern "C" void kernel_launch(void* const* d_in, const int* in_sizes, int n_in,
                              void* d_out, int out_size)
{
    (void)in_sizes; (void)n_in; (void)out_size;
    const float* xyz  = (const float*)d_in[0];
    const float* feat = (const float*)d_in[1];
    const float* P[18];
    for (int i = 0; i < 18; i++) P[i] = (const float*)d_in[2 + i];

    float* out    = (float*)d_out;
    float* newxyz = out;
    float* pooled = out + (size_t)B_ * S_ * 3;

    float* fW0;  cudaGetSymbolAddress((void**)&fW0, g_fW0);

    cudaFuncSetAttribute(front_kernel, cudaFuncAttributeMaxDynamicSharedMemorySize, FRONT_SMEM);
    cudaFuncSetAttribute(mlp_kernel,   cudaFuncAttributeMaxDynamicSharedMemorySize, MLP_SMEM_FL * 4);

    front_kernel<<<16 + 256 + 1024, 1024, FRONT_SMEM>>>(xyz, feat, P[0], newxyz);
    mlp_kernel<<<B_ * S_ / 8, 256, MLP_SMEM_FL * 4>>>(
        xyz, fW0,
        P[0],  P[1],  P[2],  P[3],  P[4],  P[5],
        P[6],  P[7],  P[8],  P[9],  P[10], P[11],
        P[12], P[13], P[14], P[15], P[16], P[17],
        pooled);
}